// round 13
// baseline (speedup 1.0000x reference)
#include <cuda_runtime.h>
#include <cuda_fp16.h>
#include <math.h>
#include <stdint.h>

#define RSQRT2 0.70710678118654752f

// ---------------- device scratch (allocation-free rule) ----------------
// BSS zero-init is load-time state. g_t*/g_nt2/g_ns2 are re-zeroed at the END
// of every kernel_launch (graph tail), so each replay starts from zeros.
// xpad's halo is never written by any kernel and stays zero forever.
__device__ float g_t1[2304];
__device__ float g_t2[2304];
__device__ float g_t3[256];
__device__ float g_nt2[3];
__device__ float g_ns2[3];
__device__ __half g_xpad[16 * 66 * 66 * 256];   // NHWC padded fp16 x (halo always 0)
__device__ __half g_bufA[16 * 64 * 64 * 256];   // conv1 output NHWC
__device__ __half g_bufB[16 * 63 * 63 * 256];   // blur(x,pad1) NHWC
__device__ __half g_bufC[16 * 65 * 65 * 256];   // blur(conv1,pad2) NHWC
__device__ __half g_wt1[256 * 9 * 256];         // [oc][khw][ic]  (unscaled fp16)
__device__ __half g_wt2[512 * 9 * 256];
__device__ __half g_wts[512 * 256];

// ---------------- helpers ----------------
__device__ __forceinline__ float warp_sum(float v) {
#pragma unroll
    for (int o = 16; o; o >>= 1) v += __shfl_down_sync(0xffffffffu, v, o);
    return v;
}

__device__ float block_sum(float v) {
    __shared__ float red[32];
    int lane = threadIdx.x & 31, w = threadIdx.x >> 5;
    v = warp_sum(v);
    if (lane == 0) red[w] = v;
    __syncthreads();
    float r = 0.f;
    if (w == 0) {
        int nw = (blockDim.x + 31) >> 5;
        r = (lane < nw) ? red[lane] : 0.f;
        r = warp_sum(r);
    }
    __syncthreads();
    return r;
}

__device__ __forceinline__ uint32_t smem_u32(const void* p) {
    uint32_t a;
    asm("{ .reg .u64 t; cvta.to.shared.u64 t, %1; cvt.u32.u64 %0, t; }" : "=r"(a) : "l"(p));
    return a;
}

__device__ __forceinline__ void sts32f(uint32_t a, float v) {
    asm volatile("st.shared.b32 [%0], %1;" :: "r"(a), "f"(v) : "memory");
}
__device__ __forceinline__ float4 lds128f(uint32_t a) {
    float4 v;
    asm volatile("ld.shared.v4.f32 {%0,%1,%2,%3}, [%4];"
                 : "=f"(v.x), "=f"(v.y), "=f"(v.z), "=f"(v.w) : "r"(a));
    return v;
}

__device__ __forceinline__ void cpa16(uint32_t s, const void* g) {
    asm volatile("cp.async.cg.shared.global [%0], [%1], 16;" :: "r"(s), "l"(g) : "memory");
}
__device__ __forceinline__ void cp_commit() {
    asm volatile("cp.async.commit_group;" ::: "memory");
}
template <int N>
__device__ __forceinline__ void cp_wait() {
    asm volatile("cp.async.wait_group %0;" :: "n"(N) : "memory");
}

__device__ __forceinline__ void ldsm4(uint32_t* r, uint32_t addr) {
    asm volatile("ldmatrix.sync.aligned.m8n8.x4.shared.b16 {%0,%1,%2,%3}, [%4];"
                 : "=r"(r[0]), "=r"(r[1]), "=r"(r[2]), "=r"(r[3]) : "r"(addr));
}

__device__ __forceinline__ void mma16816(float* c, const uint32_t* a, const uint32_t* b) {
    asm volatile(
        "mma.sync.aligned.m16n8k16.row.col.f32.f16.f16.f32 "
        "{%0,%1,%2,%3}, {%4,%5,%6,%7}, {%8,%9}, {%0,%1,%2,%3};"
        : "+f"(c[0]), "+f"(c[1]), "+f"(c[2]), "+f"(c[3])
        : "r"(a[0]), "r"(a[1]), "r"(a[2]), "r"(a[3]), "r"(b[0]), "r"(b[1]));
}

__device__ __forceinline__ float inv_sigma_of(int sigIdx) {
    float nt = sqrtf(g_nt2[sigIdx]);
    float nwt = sqrtf(g_ns2[sigIdx]);
    float nwv = nwt / (nt + 1e-12f);
    return (nwv + 1e-12f) / (nwv * nwv);
}

// ---------------- spectral norm (fused across all 3 weights) ----------------
__global__ void sn_tk_all(const float* __restrict__ w1, const float* __restrict__ u1,
                          const float* __restrict__ w2, const float* __restrict__ u2,
                          const float* __restrict__ ws, const float* __restrict__ us) {
    const int wsel = blockIdx.z;
    const float* W = (wsel == 0) ? w1 : (wsel == 1) ? w2 : ws;
    const float* u = (wsel == 0) ? u1 : (wsel == 1) ? u2 : us;
    float* t = (wsel == 0) ? g_t1 : (wsel == 1) ? g_t2 : g_t3;
    const int H = (wsel == 0) ? 256 : 512;
    const int K = (wsel == 2) ? 256 : 2304;
    int j = blockIdx.x * 256 + threadIdx.x;
    if (j >= K) return;
    int chunk = H >> 3;
    int i0 = blockIdx.y * chunk;
    int i1 = i0 + chunk;
    float s = 0.f;
    for (int i = i0; i < i1; i++)
        s = fmaf(W[(size_t)i * K + j], __ldg(u + i), s);
    atomicAdd(t + j, s);
}

__global__ void sn_sk_all(const float* __restrict__ w1, const float* __restrict__ w2,
                          const float* __restrict__ ws) {
    const int wsel = blockIdx.y;
    const float* W = (wsel == 0) ? w1 : (wsel == 1) ? w2 : ws;
    const float* t = (wsel == 0) ? g_t1 : (wsel == 1) ? g_t2 : g_t3;
    const int H = (wsel == 0) ? 256 : 512;
    const int K = (wsel == 2) ? 256 : 2304;
    const int i = blockIdx.x;
    if (i >= H) return;
    float s = 0.f;
    for (int j = threadIdx.x; j < K; j += blockDim.x)
        s = fmaf(W[(size_t)i * K + j], __ldg(t + j), s);
    s = block_sum(s);
    if (threadIdx.x == 0) atomicAdd(&g_ns2[wsel], s * s);
    if (i == 0) {
        float a = 0.f;
        for (int j = threadIdx.x; j < K; j += blockDim.x) {
            float tv = __ldg(t + j);
            a = fmaf(tv, tv, a);
        }
        a = block_sum(a);
        if (threadIdx.x == 0) atomicAdd(&g_nt2[wsel], a);
    }
}

__global__ void sn_zero_tail() {
    int t = threadIdx.x;
    for (int i = t; i < 2304; i += 256) { g_t1[i] = 0.f; g_t2[i] = 0.f; }
    if (t < 256) g_t3[t] = 0.f;
    if (t < 3) { g_nt2[t] = 0.f; g_ns2[t] = 0.f; }
}

// ---------------- merged pad + weight prep ----------------
#define PAD_BLOCKS 8192
#define PREP_N1 (256 * 256 * 9)
#define PREP_N2 (512 * 256 * 9)
#define PREP_NS (512 * 256)
#define PREP_TOTAL (PREP_N1 + PREP_N2 + PREP_NS)
#define PREP_BLOCKS ((PREP_TOTAL + 255) / 256)
#define PADPREP_BLOCKS (PAD_BLOCKS + PREP_BLOCKS)

__global__ void padprep(const float* __restrict__ x, __half* __restrict__ xp,
                        const float* __restrict__ w1, const float* __restrict__ w2,
                        const float* __restrict__ ws) {
    __shared__ float sm[64][33];
    const int bid = blockIdx.x;
    const int tid = threadIdx.x;
    if (bid < PAD_BLOCKS) {
        const int wt = bid & 1;
        const int ict = (bid >> 1) & 3;
        const int plane = bid >> 3;
        const int img = plane >> 6, h = plane & 63;
        const int w0 = wt * 32, ic0 = ict * 64;
        const int icl = tid >> 5, wl = tid & 31;
        const float* xb = x + (((size_t)img * 256 + ic0) * 64 + h) * 64 + w0;
#pragma unroll
        for (int r = 0; r < 8; r++)
            sm[icl + r * 8][wl] = xb[(size_t)(icl + r * 8) * 4096 + wl];
        __syncthreads();
        const int wIdx = tid >> 3, icq = tid & 7;
        __half hv[8];
#pragma unroll
        for (int k = 0; k < 8; k++) hv[k] = __float2half_rn(sm[icq * 8 + k][wIdx]);
        *reinterpret_cast<int4*>(
            xp + (((size_t)img * 66 + h + 1) * 66 + (w0 + wIdx + 1)) * 256 + ic0 + icq * 8) =
            *reinterpret_cast<int4*>(hv);
    } else {
        int idx = (bid - PAD_BLOCKS) * 256 + tid;
        if (idx >= PREP_TOTAL) return;
        const float* w;
        __half* wtp;
        int KHW, li;
        if (idx < PREP_N1) {
            w = w1; wtp = g_wt1; KHW = 9; li = idx;
        } else if (idx < PREP_N1 + PREP_N2) {
            w = w2; wtp = g_wt2; KHW = 9; li = idx - PREP_N1;
        } else {
            w = ws; wtp = g_wts; KHW = 1; li = idx - PREP_N1 - PREP_N2;
        }
        int khw = li % KHW;
        int t = li / KHW;
        int ic = t & 255;
        int oc = t >> 8;
        wtp[((size_t)oc * KHW + khw) * 256 + ic] = __float2half_rn(w[li]);
    }
}

// ---------------- 4x4 binomial blur, NHWC, 4 x-outputs x 8ch per thread ------
template <bool CHECK, int OFF>
__global__ void blur4_nhwc(const __half* __restrict__ in, __half* __restrict__ out,
                           int inW, int outW, int groups) {
    int idx = blockIdx.x * blockDim.x + threadIdx.x;
    int total = 16 * outW * groups * 32;
    if (idx >= total) return;
    const int icq = idx & 31;
    int t = idx >> 5;
    const int xg = t % groups; t /= groups;
    const int y = t % outW;
    const int img = t / outW;
    const int x0 = xg * 4;
    const __half* ib = in + (size_t)img * inW * inW * 256 + icq * 8;
    const float kv[4] = {1.f, 3.f, 3.f, 1.f};
    float acc[4][8];
#pragma unroll
    for (int o = 0; o < 4; o++)
#pragma unroll
        for (int q = 0; q < 8; q++) acc[o][q] = 0.f;
#pragma unroll
    for (int i = 0; i < 4; i++) {
        const int yy = y + i + OFF;
        if ((unsigned)yy >= (unsigned)inW) continue;
        const __half* rb = ib + (size_t)yy * inW * 256;
#pragma unroll
        for (int c = 0; c < 7; c++) {
            const int xx = x0 + c + OFF;
            if ((unsigned)xx >= (unsigned)inW) continue;
            int4 v = *reinterpret_cast<const int4*>(rb + (size_t)xx * 256);
            const __half* h = reinterpret_cast<const __half*>(&v);
            float hv[8];
#pragma unroll
            for (int q = 0; q < 8; q++) hv[q] = __half2float(h[q]);
#pragma unroll
            for (int o = 0; o < 4; o++) {
                const int j = c - o;
                if (j >= 0 && j < 4) {
                    const float w = kv[i] * kv[j];
#pragma unroll
                    for (int q = 0; q < 8; q++) acc[o][q] = fmaf(w, hv[q], acc[o][q]);
                }
            }
        }
    }
#pragma unroll
    for (int o = 0; o < 4; o++) {
        const int x = x0 + o;
        if (x >= outW) break;
        __half res[8];
#pragma unroll
        for (int q = 0; q < 8; q++) res[q] = __float2half_rn(acc[o][q] * (1.f / 64.f));
        *reinterpret_cast<int4*>(
            out + ((size_t)img * outW * outW + (size_t)y * outW + x) * 256 + icq * 8) =
            *reinterpret_cast<int4*>(res);
    }
}

// ---------------------------------------------------------------------------
// fp16 mma.sync implicit-GEMM conv, NHWC, cp.async 6-stage ring,
// TWO K32 stages per __syncthreads (half the barriers), 4 stages in flight
// during compute. Prefetch targets were retired two barriers ago (race-free).
// EPI: 0 = *is + bias, lrelu -> NHWC fp16
//      1 = *is + bias, lrelu -> NCHW f32
//      2 = out*rsqrt2 + acc*is*rsqrt2 -> NCHW f32
// ---------------------------------------------------------------------------
#define STAGE_BYTES 20480
#define CONV_SMEM (6 * STAGE_BYTES)

template <int KHW, int STRIDE, int EPI, int NS>
__global__ void __launch_bounds__(256, 1) conv_hmma(
    const __half* __restrict__ in, const __half* __restrict__ wt,
    const float* __restrict__ bias, void* __restrict__ outv,
    int INROW, int INIMG, int OC, int OH, int OW, int sigIdx) {
    extern __shared__ char smem[];
    const uint32_t sb = smem_u32(smem);

    const int tid = threadIdx.x;
    const int lane = tid & 31;
    const int wid = tid >> 5;
    const int wm = wid & 3;
    const int wn = wid >> 2;

    const int m0 = blockIdx.x * 128;
    const int ocb = blockIdx.y * 128;
    const int ohw = OH * OW;
    const int img = m0 / ohw;
    const int rbase = m0 - img * ohw;

    const int mIdx = tid >> 1;
    const int kq = tid & 1;
    const int m = rbase + mIdx;
    const int oh = m / OW;
    const int ow = m - oh * OW;
    const __half* abase = in + (size_t)img * INIMG + (size_t)(oh * STRIDE) * INROW +
                          (size_t)(ow * STRIDE) * 256 + kq * 16;
    const __half* bbase = wt + (size_t)(ocb + mIdx) * KHW * 256 + kq * 16;
    const uint32_t stsOff = (uint32_t)(mIdx * 80 + kq * 32);

    const int lg = lane >> 3, lr = lane & 7;
    const uint32_t rowsel = (uint32_t)(lr + ((lg >> 1) << 3));
    const uint32_t kcol = (uint32_t)((lg & 1) << 4);
    const uint32_t aLMr = (wm * 32 + rowsel) * 80 + kcol;
    const uint32_t bLMr = (wn * 64 + rowsel) * 80 + kcol;

    float c[2][8][4];
#pragma unroll
    for (int mb = 0; mb < 2; mb++)
#pragma unroll
        for (int nb = 0; nb < 8; nb++)
#pragma unroll
            for (int q = 0; q < 4; q++) c[mb][nb][q] = 0.f;

    auto CPA = [&](int s, uint32_t base) {
        const int kk = s * 32;
        const int khw = (KHW == 1) ? 0 : (kk >> 8);
        const int ic0 = kk - (khw << 8);
        int kh = 0, kw = 0;
        if (KHW == 9) { kh = khw / 3; kw = khw - kh * 3; }
        const __half* ap = abase + (size_t)kh * INROW + kw * 256 + ic0;
        cpa16(base + stsOff, ap);
        cpa16(base + stsOff + 16, ap + 8);
        const __half* bp = bbase + khw * 256 + ic0;
        cpa16(base + 10240 + stsOff, bp);
        cpa16(base + 10240 + stsOff + 16, bp + 8);
        cp_commit();
    };

    auto MMA = [&](uint32_t base) {
        const uint32_t aLM = base + aLMr;
        const uint32_t bLM = base + 10240 + bLMr;
#pragma unroll
        for (int k16 = 0; k16 < 2; k16++) {
            uint32_t a[2][4], b[8][2];
#pragma unroll
            for (int mb = 0; mb < 2; mb++) {
                uint32_t r[4];
                ldsm4(r, aLM + k16 * 32 + mb * 1280);
                a[mb][0] = r[0]; a[mb][1] = r[2]; a[mb][2] = r[1]; a[mb][3] = r[3];
            }
#pragma unroll
            for (int nbp = 0; nbp < 4; nbp++) {
                uint32_t r[4];
                ldsm4(r, bLM + k16 * 32 + nbp * 1280);
                b[nbp * 2][0] = r[0]; b[nbp * 2][1] = r[1];
                b[nbp * 2 + 1][0] = r[2]; b[nbp * 2 + 1][1] = r[3];
            }
#pragma unroll
            for (int mb = 0; mb < 2; mb++)
#pragma unroll
                for (int nb = 0; nb < 8; nb++)
                    mma16816(c[mb][nb], a[mb], b[nb]);
        }
    };

    // prologue: 4 stages in flight
    CPA(0, sb);
    if (NS > 1) CPA(1, sb + STAGE_BYTES);
    if (NS > 2) CPA(2, sb + 2 * STAGE_BYTES);
    if (NS > 3) CPA(3, sb + 3 * STAGE_BYTES);

    // pair loop, unrolled over 3 pairs (6 stages) so buffer bases are constant
    for (int s0 = 0; s0 < NS; s0 += 6) {
#pragma unroll
        for (int jp = 0; jp < 3; jp++) {
            const int s = s0 + 2 * jp;
            if ((NS % 6 != 0) && s >= NS) break;
            if (s + 2 < NS) cp_wait<2>(); else cp_wait<0>();
            __syncthreads();
            // prefetch into buffers retired 2 barriers ago
            const uint32_t pb0 = sb + ((2 * jp + 4) % 6) * STAGE_BYTES;
            const uint32_t pb1 = sb + ((2 * jp + 5) % 6) * STAGE_BYTES;
            if (s + 4 < NS) CPA(s + 4, pb0);
            if (s + 5 < NS) CPA(s + 5, pb1);
            MMA(sb + (2 * jp) * STAGE_BYTES);
            if (s + 1 < NS) MMA(sb + (2 * jp + 1) * STAGE_BYTES);
        }
    }
    __syncthreads();

    const float is = inv_sigma_of(sigIdx);
    const int erow = lane >> 2;
    const int ecolp = (lane & 3) * 2;

    if (EPI == 0) {
        __half* ob = (__half*)outv;
#pragma unroll
        for (int mb = 0; mb < 2; mb++) {
            const size_t mrow = (size_t)(m0 + wm * 32 + mb * 16 + erow);
#pragma unroll
            for (int nb = 0; nb < 8; nb++) {
                const int col = ocb + wn * 64 + nb * 8 + ecolp;
                const float bv0 = __ldg(bias + col);
                const float bv1 = __ldg(bias + col + 1);
                const float* cc = c[mb][nb];
                float v0 = fmaf(cc[0], is, bv0), v1 = fmaf(cc[1], is, bv1);
                float v2 = fmaf(cc[2], is, bv0), v3 = fmaf(cc[3], is, bv1);
                v0 = v0 > 0.f ? v0 : 0.2f * v0;
                v1 = v1 > 0.f ? v1 : 0.2f * v1;
                v2 = v2 > 0.f ? v2 : 0.2f * v2;
                v3 = v3 > 0.f ? v3 : 0.2f * v3;
                __half2 h0 = __floats2half2_rn(v0, v1);
                __half2 h1 = __floats2half2_rn(v2, v3);
                *reinterpret_cast<__half2*>(ob + mrow * 256 + col) = h0;
                *reinterpret_cast<__half2*>(ob + (mrow + 8) * 256 + col) = h1;
            }
        }
    } else {
        const float sc = is * RSQRT2;
        for (int nc = 0; nc < 4; nc++) {
            if (wn == (nc >> 1)) {
                const int nbBase = (nc & 1) * 4;
#pragma unroll
                for (int mb = 0; mb < 2; mb++) {
                    const int mrow = wm * 32 + mb * 16 + erow;
#pragma unroll
                    for (int j = 0; j < 4; j++) {
                        const int nb = nbBase + j;
                        const int ocl = j * 8 + ecolp;
                        const float* cc = c[mb][nb];
                        sts32f(sb + (uint32_t)(ocl * 544 + mrow * 4), cc[0]);
                        sts32f(sb + (uint32_t)((ocl + 1) * 544 + mrow * 4), cc[1]);
                        sts32f(sb + (uint32_t)(ocl * 544 + (mrow + 8) * 4), cc[2]);
                        sts32f(sb + (uint32_t)((ocl + 1) * 544 + (mrow + 8) * 4), cc[3]);
                    }
                }
            }
            __syncthreads();
#pragma unroll
            for (int p = 0; p < 4; p++) {
                const int idx = p * 256 + tid;
                const int ocl = idx >> 5;
                const int mq = (idx & 31) * 4;
                float4 v = lds128f(sb + (uint32_t)(ocl * 544 + mq * 4));
                const int oc = ocb + nc * 32 + ocl;
                const size_t go = ((size_t)img * OC + oc) * ohw + rbase + mq;
                if (EPI == 1) {
                    const float bv = __ldg(bias + oc);
                    v.x = fmaf(v.x, is, bv); v.y = fmaf(v.y, is, bv);
                    v.z = fmaf(v.z, is, bv); v.w = fmaf(v.w, is, bv);
                    v.x = v.x > 0.f ? v.x : 0.2f * v.x;
                    v.y = v.y > 0.f ? v.y : 0.2f * v.y;
                    v.z = v.z > 0.f ? v.z : 0.2f * v.z;
                    v.w = v.w > 0.f ? v.w : 0.2f * v.w;
                    *reinterpret_cast<float4*>((float*)outv + go) = v;
                } else {
                    float* op = (float*)outv + go;
                    float4 o = *reinterpret_cast<const float4*>(op);
                    o.x = fmaf(v.x, sc, o.x * RSQRT2);
                    o.y = fmaf(v.y, sc, o.y * RSQRT2);
                    o.z = fmaf(v.z, sc, o.z * RSQRT2);
                    o.w = fmaf(v.w, sc, o.w * RSQRT2);
                    *reinterpret_cast<float4*>(op) = o;
                }
            }
            __syncthreads();
        }
    }
}

// ---------------------------------------------------------------------------
extern "C" void kernel_launch(void* const* d_in, const int* in_sizes, int n_in,
                              void* d_out, int out_size) {
    const float* x   = (const float*)d_in[0];
    const float* w1  = (const float*)d_in[1];
    const float* u1  = (const float*)d_in[2];
    const float* b1  = (const float*)d_in[4];
    const float* w2  = (const float*)d_in[5];
    const float* u2  = (const float*)d_in[6];
    const float* b2  = (const float*)d_in[8];
    const float* wsk = (const float*)d_in[9];
    const float* us  = (const float*)d_in[10];
    float* out = (float*)d_out;

    __half *xpad, *bufA, *bufB, *bufC, *wt1, *wt2, *wts;
    cudaGetSymbolAddress((void**)&xpad, g_xpad);
    cudaGetSymbolAddress((void**)&bufA, g_bufA);
    cudaGetSymbolAddress((void**)&bufB, g_bufB);
    cudaGetSymbolAddress((void**)&bufC, g_bufC);
    cudaGetSymbolAddress((void**)&wt1, g_wt1);
    cudaGetSymbolAddress((void**)&wt2, g_wt2);
    cudaGetSymbolAddress((void**)&wts, g_wts);

    cudaFuncSetAttribute(conv_hmma<9, 1, 0, 72>,
                         cudaFuncAttributeMaxDynamicSharedMemorySize, CONV_SMEM);
    cudaFuncSetAttribute(conv_hmma<9, 2, 1, 72>,
                         cudaFuncAttributeMaxDynamicSharedMemorySize, CONV_SMEM);
    cudaFuncSetAttribute(conv_hmma<1, 2, 2, 8>,
                         cudaFuncAttributeMaxDynamicSharedMemorySize, CONV_SMEM);

    // #0: t = W^T u
    sn_tk_all<<<dim3(9, 8, 3), 256>>>(w1, u1, w2, u2, wsk, us);
    // #1: ||Wt||^2, ||t||^2
    sn_sk_all<<<dim3(512, 3), 256>>>(w1, w2, wsk);
    // #2: pad/transpose x + transpose/convert weights
    padprep<<<PADPREP_BLOCKS, 256>>>(x, xpad, w1, w2, wsk);
    // #3: conv1 (ncu sampling slot)
    conv_hmma<9, 1, 0, 72><<<dim3(512, 2), 256, CONV_SMEM>>>(
        xpad, wt1, b1, bufA, 66 * 256, 66 * 66 * 256, 256, 64, 64, 0);
    // #4: blurB (skip path): xpad (66) -> bufB (63), OFF=0
    {
        const int groups = (63 + 3) / 4;
        const int t = 16 * 63 * groups * 32;
        blur4_nhwc<false, 0><<<(t + 255) / 256, 256>>>(xpad, bufB, 66, 63, groups);
    }
    // #5: blurC: bufA (64) -> bufC (65), OFF=-2
    {
        const int groups = (65 + 3) / 4;
        const int t = 16 * 65 * groups * 32;
        blur4_nhwc<true, -2><<<(t + 255) / 256, 256>>>(bufA, bufC, 64, 65, groups);
    }
    // #6: conv2 -> out NCHW f32
    conv_hmma<9, 2, 1, 72><<<dim3(128, 4), 256, CONV_SMEM>>>(
        bufC, wt2, b2, out, 65 * 256, 65 * 65 * 256, 512, 32, 32, 1);
    // #7: skip conv: out = out*rsqrt2 + acc*is*rsqrt2
    conv_hmma<1, 2, 2, 8><<<dim3(128, 4), 256, CONV_SMEM>>>(
        bufB, wts, nullptr, out, 63 * 256, 63 * 63 * 256, 512, 32, 32, 2);
    // #8: reset SN accumulators for the next replay
    sn_zero_tail<<<1, 256>>>();
}

// round 14
// speedup vs baseline: 1.0427x; 1.0427x over previous
#include <cuda_runtime.h>
#include <cuda_fp16.h>
#include <math.h>
#include <stdint.h>

#define RSQRT2 0.70710678118654752f

// ---------------- device scratch (allocation-free rule) ----------------
// BSS zero-init is load-time state. g_t*/g_nt2/g_ns2 are re-zeroed at the END
// of every kernel_launch (graph tail), so each replay starts from zeros.
// xpad's halo is never written by any kernel and stays zero forever.
__device__ float g_t1[2304];
__device__ float g_t2[2304];
__device__ float g_t3[256];
__device__ float g_nt2[3];
__device__ float g_ns2[3];
__device__ __half g_xpad[16 * 66 * 66 * 256];   // NHWC padded fp16 x (halo always 0)
__device__ __half g_bufA[16 * 64 * 64 * 256];   // conv1 output NHWC
__device__ __half g_bufB[16 * 63 * 63 * 256];   // blur(x,pad1) NHWC
__device__ __half g_bufC[16 * 65 * 65 * 256];   // blur(conv1,pad2) NHWC
__device__ __half g_wt1[256 * 9 * 256];         // [oc][khw][ic]  (unscaled fp16)
__device__ __half g_wt2[512 * 9 * 256];
__device__ __half g_wts[512 * 256];

// ---------------- helpers ----------------
__device__ __forceinline__ float warp_sum(float v) {
#pragma unroll
    for (int o = 16; o; o >>= 1) v += __shfl_down_sync(0xffffffffu, v, o);
    return v;
}

__device__ float block_sum(float v) {
    __shared__ float red[32];
    int lane = threadIdx.x & 31, w = threadIdx.x >> 5;
    v = warp_sum(v);
    if (lane == 0) red[w] = v;
    __syncthreads();
    float r = 0.f;
    if (w == 0) {
        int nw = (blockDim.x + 31) >> 5;
        r = (lane < nw) ? red[lane] : 0.f;
        r = warp_sum(r);
    }
    __syncthreads();
    return r;
}

__device__ __forceinline__ uint32_t smem_u32(const void* p) {
    uint32_t a;
    asm("{ .reg .u64 t; cvta.to.shared.u64 t, %1; cvt.u32.u64 %0, t; }" : "=r"(a) : "l"(p));
    return a;
}

__device__ __forceinline__ void sts32f(uint32_t a, float v) {
    asm volatile("st.shared.b32 [%0], %1;" :: "r"(a), "f"(v) : "memory");
}
__device__ __forceinline__ float4 lds128f(uint32_t a) {
    float4 v;
    asm volatile("ld.shared.v4.f32 {%0,%1,%2,%3}, [%4];"
                 : "=f"(v.x), "=f"(v.y), "=f"(v.z), "=f"(v.w) : "r"(a));
    return v;
}

__device__ __forceinline__ void cpa16(uint32_t s, const void* g) {
    asm volatile("cp.async.cg.shared.global [%0], [%1], 16;" :: "r"(s), "l"(g) : "memory");
}
__device__ __forceinline__ void cp_commit() {
    asm volatile("cp.async.commit_group;" ::: "memory");
}
template <int N>
__device__ __forceinline__ void cp_wait() {
    asm volatile("cp.async.wait_group %0;" :: "n"(N) : "memory");
}

__device__ __forceinline__ void ldsm4(uint32_t* r, uint32_t addr) {
    asm volatile("ldmatrix.sync.aligned.m8n8.x4.shared.b16 {%0,%1,%2,%3}, [%4];"
                 : "=r"(r[0]), "=r"(r[1]), "=r"(r[2]), "=r"(r[3]) : "r"(addr));
}

__device__ __forceinline__ void mma16816(float* c, const uint32_t* a, const uint32_t* b) {
    asm volatile(
        "mma.sync.aligned.m16n8k16.row.col.f32.f16.f16.f32 "
        "{%0,%1,%2,%3}, {%4,%5,%6,%7}, {%8,%9}, {%0,%1,%2,%3};"
        : "+f"(c[0]), "+f"(c[1]), "+f"(c[2]), "+f"(c[3])
        : "r"(a[0]), "r"(a[1]), "r"(a[2]), "r"(a[3]), "r"(b[0]), "r"(b[1]));
}

__device__ __forceinline__ float inv_sigma_of(int sigIdx) {
    float nt = sqrtf(g_nt2[sigIdx]);
    float nwt = sqrtf(g_ns2[sigIdx]);
    float nwv = nwt / (nt + 1e-12f);
    return (nwv + 1e-12f) / (nwv * nwv);
}

// ---------------- spectral norm (fused across all 3 weights) ----------------
__global__ void sn_tk_all(const float* __restrict__ w1, const float* __restrict__ u1,
                          const float* __restrict__ w2, const float* __restrict__ u2,
                          const float* __restrict__ ws, const float* __restrict__ us) {
    const int wsel = blockIdx.z;
    const float* W = (wsel == 0) ? w1 : (wsel == 1) ? w2 : ws;
    const float* u = (wsel == 0) ? u1 : (wsel == 1) ? u2 : us;
    float* t = (wsel == 0) ? g_t1 : (wsel == 1) ? g_t2 : g_t3;
    const int H = (wsel == 0) ? 256 : 512;
    const int K = (wsel == 2) ? 256 : 2304;
    int j = blockIdx.x * 256 + threadIdx.x;
    if (j >= K) return;
    int chunk = H >> 3;
    int i0 = blockIdx.y * chunk;
    int i1 = i0 + chunk;
    float s = 0.f;
    for (int i = i0; i < i1; i++)
        s = fmaf(W[(size_t)i * K + j], __ldg(u + i), s);
    atomicAdd(t + j, s);
}

__global__ void sn_sk_all(const float* __restrict__ w1, const float* __restrict__ w2,
                          const float* __restrict__ ws) {
    const int wsel = blockIdx.y;
    const float* W = (wsel == 0) ? w1 : (wsel == 1) ? w2 : ws;
    const float* t = (wsel == 0) ? g_t1 : (wsel == 1) ? g_t2 : g_t3;
    const int H = (wsel == 0) ? 256 : 512;
    const int K = (wsel == 2) ? 256 : 2304;
    const int i = blockIdx.x;
    if (i >= H) return;
    float s = 0.f;
    for (int j = threadIdx.x; j < K; j += blockDim.x)
        s = fmaf(W[(size_t)i * K + j], __ldg(t + j), s);
    s = block_sum(s);
    if (threadIdx.x == 0) atomicAdd(&g_ns2[wsel], s * s);
    if (i == 0) {
        float a = 0.f;
        for (int j = threadIdx.x; j < K; j += blockDim.x) {
            float tv = __ldg(t + j);
            a = fmaf(tv, tv, a);
        }
        a = block_sum(a);
        if (threadIdx.x == 0) atomicAdd(&g_nt2[wsel], a);
    }
}

__global__ void sn_zero_tail() {
    int t = threadIdx.x;
    for (int i = t; i < 2304; i += 256) { g_t1[i] = 0.f; g_t2[i] = 0.f; }
    if (t < 256) g_t3[t] = 0.f;
    if (t < 3) { g_nt2[t] = 0.f; g_ns2[t] = 0.f; }
}

// ---------------- merged pad + weight prep ----------------
#define PAD_BLOCKS 8192
#define PREP_N1 (256 * 256 * 9)
#define PREP_N2 (512 * 256 * 9)
#define PREP_NS (512 * 256)
#define PREP_TOTAL (PREP_N1 + PREP_N2 + PREP_NS)
#define PREP_BLOCKS ((PREP_TOTAL + 255) / 256)
#define PADPREP_BLOCKS (PAD_BLOCKS + PREP_BLOCKS)

__global__ void padprep(const float* __restrict__ x, __half* __restrict__ xp,
                        const float* __restrict__ w1, const float* __restrict__ w2,
                        const float* __restrict__ ws) {
    __shared__ float sm[64][33];
    const int bid = blockIdx.x;
    const int tid = threadIdx.x;
    if (bid < PAD_BLOCKS) {
        const int wt = bid & 1;
        const int ict = (bid >> 1) & 3;
        const int plane = bid >> 3;
        const int img = plane >> 6, h = plane & 63;
        const int w0 = wt * 32, ic0 = ict * 64;
        const int icl = tid >> 5, wl = tid & 31;
        const float* xb = x + (((size_t)img * 256 + ic0) * 64 + h) * 64 + w0;
#pragma unroll
        for (int r = 0; r < 8; r++)
            sm[icl + r * 8][wl] = xb[(size_t)(icl + r * 8) * 4096 + wl];
        __syncthreads();
        const int wIdx = tid >> 3, icq = tid & 7;
        __half hv[8];
#pragma unroll
        for (int k = 0; k < 8; k++) hv[k] = __float2half_rn(sm[icq * 8 + k][wIdx]);
        *reinterpret_cast<int4*>(
            xp + (((size_t)img * 66 + h + 1) * 66 + (w0 + wIdx + 1)) * 256 + ic0 + icq * 8) =
            *reinterpret_cast<int4*>(hv);
    } else {
        int idx = (bid - PAD_BLOCKS) * 256 + tid;
        if (idx >= PREP_TOTAL) return;
        const float* w;
        __half* wtp;
        int KHW, li;
        if (idx < PREP_N1) {
            w = w1; wtp = g_wt1; KHW = 9; li = idx;
        } else if (idx < PREP_N1 + PREP_N2) {
            w = w2; wtp = g_wt2; KHW = 9; li = idx - PREP_N1;
        } else {
            w = ws; wtp = g_wts; KHW = 1; li = idx - PREP_N1 - PREP_N2;
        }
        int khw = li % KHW;
        int t = li / KHW;
        int ic = t & 255;
        int oc = t >> 8;
        wtp[((size_t)oc * KHW + khw) * 256 + ic] = __float2half_rn(w[li]);
    }
}

// ---------------- 4x4 binomial blur, NHWC, 4 x-outputs x 8ch per thread ------
template <bool CHECK, int OFF>
__global__ void blur4_nhwc(const __half* __restrict__ in, __half* __restrict__ out,
                           int inW, int outW, int groups) {
    int idx = blockIdx.x * blockDim.x + threadIdx.x;
    int total = 16 * outW * groups * 32;
    if (idx >= total) return;
    const int icq = idx & 31;
    int t = idx >> 5;
    const int xg = t % groups; t /= groups;
    const int y = t % outW;
    const int img = t / outW;
    const int x0 = xg * 4;
    const __half* ib = in + (size_t)img * inW * inW * 256 + icq * 8;
    const float kv[4] = {1.f, 3.f, 3.f, 1.f};
    float acc[4][8];
#pragma unroll
    for (int o = 0; o < 4; o++)
#pragma unroll
        for (int q = 0; q < 8; q++) acc[o][q] = 0.f;
#pragma unroll
    for (int i = 0; i < 4; i++) {
        const int yy = y + i + OFF;
        if ((unsigned)yy >= (unsigned)inW) continue;
        const __half* rb = ib + (size_t)yy * inW * 256;
#pragma unroll
        for (int c = 0; c < 7; c++) {
            const int xx = x0 + c + OFF;
            if ((unsigned)xx >= (unsigned)inW) continue;
            int4 v = *reinterpret_cast<const int4*>(rb + (size_t)xx * 256);
            const __half* h = reinterpret_cast<const __half*>(&v);
            float hv[8];
#pragma unroll
            for (int q = 0; q < 8; q++) hv[q] = __half2float(h[q]);
#pragma unroll
            for (int o = 0; o < 4; o++) {
                const int j = c - o;
                if (j >= 0 && j < 4) {
                    const float w = kv[i] * kv[j];
#pragma unroll
                    for (int q = 0; q < 8; q++) acc[o][q] = fmaf(w, hv[q], acc[o][q]);
                }
            }
        }
    }
#pragma unroll
    for (int o = 0; o < 4; o++) {
        const int x = x0 + o;
        if (x >= outW) break;
        __half res[8];
#pragma unroll
        for (int q = 0; q < 8; q++) res[q] = __float2half_rn(acc[o][q] * (1.f / 64.f));
        *reinterpret_cast<int4*>(
            out + ((size_t)img * outW * outW + (size_t)y * outW + x) * 256 + icq * 8) =
            *reinterpret_cast<int4*>(res);
    }
}

// ---------------------------------------------------------------------------
// fp16 mma.sync implicit-GEMM conv, NHWC, cp.async 3-stage ring of K64 stages.
// Stage = A[128][k64] pitch 144 + B[128][k64] pitch 144 = 36864 B.
// Ring = 110592 B; 2 CTAs/SM (221184 B) keeps occupancy while halving
// barriers vs K32 staging. R12 schedule: wait<1> -> sync -> CPA(s+2) -> MMA(s).
// EPI: 0 = *is + bias, lrelu -> NHWC fp16
//      1 = *is + bias, lrelu -> NCHW f32
//      2 = out*rsqrt2 + acc*is*rsqrt2 -> NCHW f32
// ---------------------------------------------------------------------------
#define APITCH 144
#define AMAT_BYTES (128 * APITCH)      // 18432
#define STAGE_BYTES (2 * AMAT_BYTES)   // 36864
#define CONV_SMEM (3 * STAGE_BYTES)    // 110592

template <int KHW, int STRIDE, int EPI, int NS>
__global__ void __launch_bounds__(256, 2) conv_hmma(
    const __half* __restrict__ in, const __half* __restrict__ wt,
    const float* __restrict__ bias, void* __restrict__ outv,
    int INROW, int INIMG, int OC, int OH, int OW, int sigIdx) {
    extern __shared__ char smem[];
    const uint32_t sb = smem_u32(smem);

    const int tid = threadIdx.x;
    const int lane = tid & 31;
    const int wid = tid >> 5;
    const int wm = wid & 3;
    const int wn = wid >> 2;

    const int m0 = blockIdx.x * 128;
    const int ocb = blockIdx.y * 128;
    const int ohw = OH * OW;
    const int img = m0 / ohw;
    const int rbase = m0 - img * ohw;

    // gather mapping: thread -> (row mIdx, 64-byte half kq of the 128B k-row)
    const int mIdx = tid >> 1;
    const int kq = tid & 1;
    const int m = rbase + mIdx;
    const int oh = m / OW;
    const int ow = m - oh * OW;
    const __half* abase = in + (size_t)img * INIMG + (size_t)(oh * STRIDE) * INROW +
                          (size_t)(ow * STRIDE) * 256 + kq * 32;
    const __half* bbase = wt + (size_t)(ocb + mIdx) * KHW * 256 + kq * 32;
    const uint32_t stsOff = (uint32_t)(mIdx * APITCH + kq * 64);

    // ldmatrix addressing (non-trans), pitch 144 (conflict-free)
    const int lg = lane >> 3, lr = lane & 7;
    const uint32_t rowsel = (uint32_t)(lr + ((lg >> 1) << 3));
    const uint32_t kcol = (uint32_t)((lg & 1) << 4);
    const uint32_t aLMr = (wm * 32 + rowsel) * APITCH + kcol;
    const uint32_t bLMr = (wn * 64 + rowsel) * APITCH + kcol;

    float c[2][8][4];
#pragma unroll
    for (int mb = 0; mb < 2; mb++)
#pragma unroll
        for (int nb = 0; nb < 8; nb++)
#pragma unroll
            for (int q = 0; q < 4; q++) c[mb][nb][q] = 0.f;

    auto CPA = [&](int s, uint32_t base) {
        const int kk = s * 64;
        const int khw = (KHW == 1) ? 0 : (kk >> 8);
        const int ic0 = kk - (khw << 8);     // 64-aligned, stays within one khw
        int kh = 0, kw = 0;
        if (KHW == 9) { kh = khw / 3; kw = khw - kh * 3; }
        const __half* ap = abase + (size_t)kh * INROW + kw * 256 + ic0;
        const uint32_t ao = base + stsOff;
        cpa16(ao, ap);
        cpa16(ao + 16, ap + 8);
        cpa16(ao + 32, ap + 16);
        cpa16(ao + 48, ap + 24);
        const __half* bp = bbase + khw * 256 + ic0;
        const uint32_t bo = base + AMAT_BYTES + stsOff;
        cpa16(bo, bp);
        cpa16(bo + 16, bp + 8);
        cpa16(bo + 32, bp + 16);
        cpa16(bo + 48, bp + 24);
        cp_commit();
    };

    auto MMA = [&](uint32_t base) {
        const uint32_t aLM = base + aLMr;
        const uint32_t bLM = base + AMAT_BYTES + bLMr;
#pragma unroll
        for (int k16 = 0; k16 < 4; k16++) {
            uint32_t a[2][4], b[8][2];
#pragma unroll
            for (int mb = 0; mb < 2; mb++) {
                uint32_t r[4];
                ldsm4(r, aLM + k16 * 32 + mb * 16 * APITCH);
                a[mb][0] = r[0]; a[mb][1] = r[2]; a[mb][2] = r[1]; a[mb][3] = r[3];
            }
#pragma unroll
            for (int nbp = 0; nbp < 4; nbp++) {
                uint32_t r[4];
                ldsm4(r, bLM + k16 * 32 + nbp * 16 * APITCH);
                b[nbp * 2][0] = r[0]; b[nbp * 2][1] = r[1];
                b[nbp * 2 + 1][0] = r[2]; b[nbp * 2 + 1][1] = r[3];
            }
#pragma unroll
            for (int mb = 0; mb < 2; mb++)
#pragma unroll
                for (int nb = 0; nb < 8; nb++)
                    mma16816(c[mb][nb], a[mb], b[nb]);
        }
    };

    CPA(0, sb);
    if (NS > 1) CPA(1, sb + STAGE_BYTES);
    // 3-stage ring, unrolled x3 so buffer bases are compile-time constants
    for (int s0 = 0; s0 < NS; s0 += 3) {
#pragma unroll
        for (int j = 0; j < 3; j++) {
            const int s = s0 + j;
            if ((NS % 3 != 0) && s >= NS) break;
            if (s + 1 < NS) cp_wait<1>(); else cp_wait<0>();
            __syncthreads();
            if (s + 2 < NS) CPA(s + 2, sb + ((j + 2) % 3) * STAGE_BYTES);
            MMA(sb + j * STAGE_BYTES);
        }
    }
    __syncthreads();

    const float is = inv_sigma_of(sigIdx);
    const int erow = lane >> 2;
    const int ecolp = (lane & 3) * 2;

    if (EPI == 0) {
        __half* ob = (__half*)outv;
#pragma unroll
        for (int mb = 0; mb < 2; mb++) {
            const size_t mrow = (size_t)(m0 + wm * 32 + mb * 16 + erow);
#pragma unroll
            for (int nb = 0; nb < 8; nb++) {
                const int col = ocb + wn * 64 + nb * 8 + ecolp;
                const float bv0 = __ldg(bias + col);
                const float bv1 = __ldg(bias + col + 1);
                const float* cc = c[mb][nb];
                float v0 = fmaf(cc[0], is, bv0), v1 = fmaf(cc[1], is, bv1);
                float v2 = fmaf(cc[2], is, bv0), v3 = fmaf(cc[3], is, bv1);
                v0 = v0 > 0.f ? v0 : 0.2f * v0;
                v1 = v1 > 0.f ? v1 : 0.2f * v1;
                v2 = v2 > 0.f ? v2 : 0.2f * v2;
                v3 = v3 > 0.f ? v3 : 0.2f * v3;
                __half2 h0 = __floats2half2_rn(v0, v1);
                __half2 h1 = __floats2half2_rn(v2, v3);
                *reinterpret_cast<__half2*>(ob + mrow * 256 + col) = h0;
                *reinterpret_cast<__half2*>(ob + (mrow + 8) * 256 + col) = h1;
            }
        }
    } else {
        const float sc = is * RSQRT2;
        for (int nc = 0; nc < 4; nc++) {
            if (wn == (nc >> 1)) {
                const int nbBase = (nc & 1) * 4;
#pragma unroll
                for (int mb = 0; mb < 2; mb++) {
                    const int mrow = wm * 32 + mb * 16 + erow;
#pragma unroll
                    for (int j = 0; j < 4; j++) {
                        const int nb = nbBase + j;
                        const int ocl = j * 8 + ecolp;
                        const float* cc = c[mb][nb];
                        sts32f(sb + (uint32_t)(ocl * 544 + mrow * 4), cc[0]);
                        sts32f(sb + (uint32_t)((ocl + 1) * 544 + mrow * 4), cc[1]);
                        sts32f(sb + (uint32_t)(ocl * 544 + (mrow + 8) * 4), cc[2]);
                        sts32f(sb + (uint32_t)((ocl + 1) * 544 + (mrow + 8) * 4), cc[3]);
                    }
                }
            }
            __syncthreads();
#pragma unroll
            for (int p = 0; p < 4; p++) {
                const int idx = p * 256 + tid;
                const int ocl = idx >> 5;
                const int mq = (idx & 31) * 4;
                float4 v = lds128f(sb + (uint32_t)(ocl * 544 + mq * 4));
                const int oc = ocb + nc * 32 + ocl;
                const size_t go = ((size_t)img * OC + oc) * ohw + rbase + mq;
                if (EPI == 1) {
                    const float bv = __ldg(bias + oc);
                    v.x = fmaf(v.x, is, bv); v.y = fmaf(v.y, is, bv);
                    v.z = fmaf(v.z, is, bv); v.w = fmaf(v.w, is, bv);
                    v.x = v.x > 0.f ? v.x : 0.2f * v.x;
                    v.y = v.y > 0.f ? v.y : 0.2f * v.y;
                    v.z = v.z > 0.f ? v.z : 0.2f * v.z;
                    v.w = v.w > 0.f ? v.w : 0.2f * v.w;
                    *reinterpret_cast<float4*>((float*)outv + go) = v;
                } else {
                    float* op = (float*)outv + go;
                    float4 o = *reinterpret_cast<const float4*>(op);
                    o.x = fmaf(v.x, sc, o.x * RSQRT2);
                    o.y = fmaf(v.y, sc, o.y * RSQRT2);
                    o.z = fmaf(v.z, sc, o.z * RSQRT2);
                    o.w = fmaf(v.w, sc, o.w * RSQRT2);
                    *reinterpret_cast<float4*>(op) = o;
                }
            }
            __syncthreads();
        }
    }
}

// ---------------------------------------------------------------------------
extern "C" void kernel_launch(void* const* d_in, const int* in_sizes, int n_in,
                              void* d_out, int out_size) {
    const float* x   = (const float*)d_in[0];
    const float* w1  = (const float*)d_in[1];
    const float* u1  = (const float*)d_in[2];
    const float* b1  = (const float*)d_in[4];
    const float* w2  = (const float*)d_in[5];
    const float* u2  = (const float*)d_in[6];
    const float* b2  = (const float*)d_in[8];
    const float* wsk = (const float*)d_in[9];
    const float* us  = (const float*)d_in[10];
    float* out = (float*)d_out;

    __half *xpad, *bufA, *bufB, *bufC, *wt1, *wt2, *wts;
    cudaGetSymbolAddress((void**)&xpad, g_xpad);
    cudaGetSymbolAddress((void**)&bufA, g_bufA);
    cudaGetSymbolAddress((void**)&bufB, g_bufB);
    cudaGetSymbolAddress((void**)&bufC, g_bufC);
    cudaGetSymbolAddress((void**)&wt1, g_wt1);
    cudaGetSymbolAddress((void**)&wt2, g_wt2);
    cudaGetSymbolAddress((void**)&wts, g_wts);

    cudaFuncSetAttribute(conv_hmma<9, 1, 0, 36>,
                         cudaFuncAttributeMaxDynamicSharedMemorySize, CONV_SMEM);
    cudaFuncSetAttribute(conv_hmma<9, 2, 1, 36>,
                         cudaFuncAttributeMaxDynamicSharedMemorySize, CONV_SMEM);
    cudaFuncSetAttribute(conv_hmma<1, 2, 2, 4>,
                         cudaFuncAttributeMaxDynamicSharedMemorySize, CONV_SMEM);

    // #0: t = W^T u
    sn_tk_all<<<dim3(9, 8, 3), 256>>>(w1, u1, w2, u2, wsk, us);
    // #1: ||Wt||^2, ||t||^2
    sn_sk_all<<<dim3(512, 3), 256>>>(w1, w2, wsk);
    // #2: pad/transpose x + transpose/convert weights
    padprep<<<PADPREP_BLOCKS, 256>>>(x, xpad, w1, w2, wsk);
    // #3: conv1 (ncu sampling slot)
    conv_hmma<9, 1, 0, 36><<<dim3(512, 2), 256, CONV_SMEM>>>(
        xpad, wt1, b1, bufA, 66 * 256, 66 * 66 * 256, 256, 64, 64, 0);
    // #4: blurB (skip path): xpad (66) -> bufB (63), OFF=0
    {
        const int groups = (63 + 3) / 4;
        const int t = 16 * 63 * groups * 32;
        blur4_nhwc<false, 0><<<(t + 255) / 256, 256>>>(xpad, bufB, 66, 63, groups);
    }
    // #5: blurC: bufA (64) -> bufC (65), OFF=-2
    {
        const int groups = (65 + 3) / 4;
        const int t = 16 * 65 * groups * 32;
        blur4_nhwc<true, -2><<<(t + 255) / 256, 256>>>(bufA, bufC, 64, 65, groups);
    }
    // #6: conv2 -> out NCHW f32
    conv_hmma<9, 2, 1, 36><<<dim3(128, 4), 256, CONV_SMEM>>>(
        bufC, wt2, b2, out, 65 * 256, 65 * 65 * 256, 512, 32, 32, 1);
    // #7: skip conv: out = out*rsqrt2 + acc*is*rsqrt2
    conv_hmma<1, 2, 2, 4><<<dim3(128, 4), 256, CONV_SMEM>>>(
        bufB, wts, nullptr, out, 63 * 256, 63 * 63 * 256, 512, 32, 32, 2);
    // #8: reset SN accumulators for the next replay
    sn_zero_tail<<<1, 256>>>();
}

// round 15
// speedup vs baseline: 1.1554x; 1.1081x over previous
#include <cuda_runtime.h>
#include <cuda_fp16.h>
#include <math.h>
#include <stdint.h>

#define RSQRT2 0.70710678118654752f

// ---------------- device scratch (allocation-free rule) ----------------
// BSS zero-init is load-time state. g_t*/g_nt2/g_ns2 are re-zeroed at the END
// of every kernel_launch (graph tail), so each replay starts from zeros.
// xpad's halo is never written by any kernel and stays zero forever.
__device__ float g_t1[2304];
__device__ float g_t2[2304];
__device__ float g_t3[256];
__device__ float g_nt2[3];
__device__ float g_ns2[3];
__device__ __half g_xpad[16 * 66 * 66 * 256];   // NHWC padded fp16 x (halo always 0)
__device__ __half g_bufA[16 * 64 * 64 * 256];   // conv1 output NHWC
__device__ __half g_bufB[16 * 63 * 63 * 256];   // blur(x,pad1) NHWC
__device__ __half g_bufC[16 * 65 * 65 * 256];   // blur(conv1,pad2) NHWC
__device__ __half g_wt1[256 * 9 * 256];         // [oc][khw][ic]  (unscaled fp16)
__device__ __half g_wt2[512 * 9 * 256];
__device__ __half g_wts[512 * 256];

// ---------------- helpers ----------------
__device__ __forceinline__ float warp_sum(float v) {
#pragma unroll
    for (int o = 16; o; o >>= 1) v += __shfl_down_sync(0xffffffffu, v, o);
    return v;
}

__device__ float block_sum(float v) {
    __shared__ float red[32];
    int lane = threadIdx.x & 31, w = threadIdx.x >> 5;
    v = warp_sum(v);
    if (lane == 0) red[w] = v;
    __syncthreads();
    float r = 0.f;
    if (w == 0) {
        int nw = (blockDim.x + 31) >> 5;
        r = (lane < nw) ? red[lane] : 0.f;
        r = warp_sum(r);
    }
    __syncthreads();
    return r;
}

__device__ __forceinline__ uint32_t smem_u32(const void* p) {
    uint32_t a;
    asm("{ .reg .u64 t; cvta.to.shared.u64 t, %1; cvt.u32.u64 %0, t; }" : "=r"(a) : "l"(p));
    return a;
}

__device__ __forceinline__ void sts32f(uint32_t a, float v) {
    asm volatile("st.shared.b32 [%0], %1;" :: "r"(a), "f"(v) : "memory");
}
__device__ __forceinline__ float4 lds128f(uint32_t a) {
    float4 v;
    asm volatile("ld.shared.v4.f32 {%0,%1,%2,%3}, [%4];"
                 : "=f"(v.x), "=f"(v.y), "=f"(v.z), "=f"(v.w) : "r"(a));
    return v;
}

__device__ __forceinline__ void cpa16(uint32_t s, const void* g) {
    asm volatile("cp.async.cg.shared.global [%0], [%1], 16;" :: "r"(s), "l"(g) : "memory");
}
__device__ __forceinline__ void cp_commit() {
    asm volatile("cp.async.commit_group;" ::: "memory");
}
template <int N>
__device__ __forceinline__ void cp_wait() {
    asm volatile("cp.async.wait_group %0;" :: "n"(N) : "memory");
}

__device__ __forceinline__ void ldsm4(uint32_t* r, uint32_t addr) {
    asm volatile("ldmatrix.sync.aligned.m8n8.x4.shared.b16 {%0,%1,%2,%3}, [%4];"
                 : "=r"(r[0]), "=r"(r[1]), "=r"(r[2]), "=r"(r[3]) : "r"(addr));
}

__device__ __forceinline__ void mma16816(float* c, const uint32_t* a, const uint32_t* b) {
    asm volatile(
        "mma.sync.aligned.m16n8k16.row.col.f32.f16.f16.f32 "
        "{%0,%1,%2,%3}, {%4,%5,%6,%7}, {%8,%9}, {%0,%1,%2,%3};"
        : "+f"(c[0]), "+f"(c[1]), "+f"(c[2]), "+f"(c[3])
        : "r"(a[0]), "r"(a[1]), "r"(a[2]), "r"(a[3]), "r"(b[0]), "r"(b[1]));
}

__device__ __forceinline__ float inv_sigma_of(int sigIdx) {
    float nt = sqrtf(g_nt2[sigIdx]);
    float nwt = sqrtf(g_ns2[sigIdx]);
    float nwv = nwt / (nt + 1e-12f);
    return (nwv + 1e-12f) / (nwv * nwv);
}

// ---------------- spectral norm (fused across all 3 weights) ----------------
__global__ void sn_tk_all(const float* __restrict__ w1, const float* __restrict__ u1,
                          const float* __restrict__ w2, const float* __restrict__ u2,
                          const float* __restrict__ ws, const float* __restrict__ us) {
    const int wsel = blockIdx.z;
    const float* W = (wsel == 0) ? w1 : (wsel == 1) ? w2 : ws;
    const float* u = (wsel == 0) ? u1 : (wsel == 1) ? u2 : us;
    float* t = (wsel == 0) ? g_t1 : (wsel == 1) ? g_t2 : g_t3;
    const int H = (wsel == 0) ? 256 : 512;
    const int K = (wsel == 2) ? 256 : 2304;
    int j = blockIdx.x * 256 + threadIdx.x;
    if (j >= K) return;
    int chunk = H >> 3;
    int i0 = blockIdx.y * chunk;
    int i1 = i0 + chunk;
    float s = 0.f;
    for (int i = i0; i < i1; i++)
        s = fmaf(W[(size_t)i * K + j], __ldg(u + i), s);
    atomicAdd(t + j, s);
}

__global__ void sn_sk_all(const float* __restrict__ w1, const float* __restrict__ w2,
                          const float* __restrict__ ws) {
    const int wsel = blockIdx.y;
    const float* W = (wsel == 0) ? w1 : (wsel == 1) ? w2 : ws;
    const float* t = (wsel == 0) ? g_t1 : (wsel == 1) ? g_t2 : g_t3;
    const int H = (wsel == 0) ? 256 : 512;
    const int K = (wsel == 2) ? 256 : 2304;
    const int i = blockIdx.x;
    if (i >= H) return;
    float s = 0.f;
    for (int j = threadIdx.x; j < K; j += blockDim.x)
        s = fmaf(W[(size_t)i * K + j], __ldg(t + j), s);
    s = block_sum(s);
    if (threadIdx.x == 0) atomicAdd(&g_ns2[wsel], s * s);
    if (i == 0) {
        float a = 0.f;
        for (int j = threadIdx.x; j < K; j += blockDim.x) {
            float tv = __ldg(t + j);
            a = fmaf(tv, tv, a);
        }
        a = block_sum(a);
        if (threadIdx.x == 0) atomicAdd(&g_nt2[wsel], a);
    }
}

__global__ void sn_zero_tail() {
    int t = threadIdx.x;
    for (int i = t; i < 2304; i += 256) { g_t1[i] = 0.f; g_t2[i] = 0.f; }
    if (t < 256) g_t3[t] = 0.f;
    if (t < 3) { g_nt2[t] = 0.f; g_ns2[t] = 0.f; }
}

// ---------------- merged pad + weight prep ----------------
#define PAD_BLOCKS 8192
#define PREP_N1 (256 * 256 * 9)
#define PREP_N2 (512 * 256 * 9)
#define PREP_NS (512 * 256)
#define PREP_TOTAL (PREP_N1 + PREP_N2 + PREP_NS)
#define PREP_BLOCKS ((PREP_TOTAL + 255) / 256)
#define PADPREP_BLOCKS (PAD_BLOCKS + PREP_BLOCKS)

__global__ void padprep(const float* __restrict__ x, __half* __restrict__ xp,
                        const float* __restrict__ w1, const float* __restrict__ w2,
                        const float* __restrict__ ws) {
    __shared__ float sm[64][33];
    const int bid = blockIdx.x;
    const int tid = threadIdx.x;
    if (bid < PAD_BLOCKS) {
        const int wt = bid & 1;
        const int ict = (bid >> 1) & 3;
        const int plane = bid >> 3;
        const int img = plane >> 6, h = plane & 63;
        const int w0 = wt * 32, ic0 = ict * 64;
        const int icl = tid >> 5, wl = tid & 31;
        const float* xb = x + (((size_t)img * 256 + ic0) * 64 + h) * 64 + w0;
#pragma unroll
        for (int r = 0; r < 8; r++)
            sm[icl + r * 8][wl] = xb[(size_t)(icl + r * 8) * 4096 + wl];
        __syncthreads();
        const int wIdx = tid >> 3, icq = tid & 7;
        __half hv[8];
#pragma unroll
        for (int k = 0; k < 8; k++) hv[k] = __float2half_rn(sm[icq * 8 + k][wIdx]);
        *reinterpret_cast<int4*>(
            xp + (((size_t)img * 66 + h + 1) * 66 + (w0 + wIdx + 1)) * 256 + ic0 + icq * 8) =
            *reinterpret_cast<int4*>(hv);
    } else {
        int idx = (bid - PAD_BLOCKS) * 256 + tid;
        if (idx >= PREP_TOTAL) return;
        const float* w;
        __half* wtp;
        int KHW, li;
        if (idx < PREP_N1) {
            w = w1; wtp = g_wt1; KHW = 9; li = idx;
        } else if (idx < PREP_N1 + PREP_N2) {
            w = w2; wtp = g_wt2; KHW = 9; li = idx - PREP_N1;
        } else {
            w = ws; wtp = g_wts; KHW = 1; li = idx - PREP_N1 - PREP_N2;
        }
        int khw = li % KHW;
        int t = li / KHW;
        int ic = t & 255;
        int oc = t >> 8;
        wtp[((size_t)oc * KHW + khw) * 256 + ic] = __float2half_rn(w[li]);
    }
}

// ---------------- 4x4 binomial blur, NHWC, 4 x-outputs x 8ch per thread ------
template <bool CHECK, int OFF>
__global__ void blur4_nhwc(const __half* __restrict__ in, __half* __restrict__ out,
                           int inW, int outW, int groups) {
    int idx = blockIdx.x * blockDim.x + threadIdx.x;
    int total = 16 * outW * groups * 32;
    if (idx >= total) return;
    const int icq = idx & 31;
    int t = idx >> 5;
    const int xg = t % groups; t /= groups;
    const int y = t % outW;
    const int img = t / outW;
    const int x0 = xg * 4;
    const __half* ib = in + (size_t)img * inW * inW * 256 + icq * 8;
    const float kv[4] = {1.f, 3.f, 3.f, 1.f};
    float acc[4][8];
#pragma unroll
    for (int o = 0; o < 4; o++)
#pragma unroll
        for (int q = 0; q < 8; q++) acc[o][q] = 0.f;
#pragma unroll
    for (int i = 0; i < 4; i++) {
        const int yy = y + i + OFF;
        if ((unsigned)yy >= (unsigned)inW) continue;
        const __half* rb = ib + (size_t)yy * inW * 256;
#pragma unroll
        for (int c = 0; c < 7; c++) {
            const int xx = x0 + c + OFF;
            if ((unsigned)xx >= (unsigned)inW) continue;
            int4 v = *reinterpret_cast<const int4*>(rb + (size_t)xx * 256);
            const __half* h = reinterpret_cast<const __half*>(&v);
            float hv[8];
#pragma unroll
            for (int q = 0; q < 8; q++) hv[q] = __half2float(h[q]);
#pragma unroll
            for (int o = 0; o < 4; o++) {
                const int j = c - o;
                if (j >= 0 && j < 4) {
                    const float w = kv[i] * kv[j];
#pragma unroll
                    for (int q = 0; q < 8; q++) acc[o][q] = fmaf(w, hv[q], acc[o][q]);
                }
            }
        }
    }
#pragma unroll
    for (int o = 0; o < 4; o++) {
        const int x = x0 + o;
        if (x >= outW) break;
        __half res[8];
#pragma unroll
        for (int q = 0; q < 8; q++) res[q] = __float2half_rn(acc[o][q] * (1.f / 64.f));
        *reinterpret_cast<int4*>(
            out + ((size_t)img * outW * outW + (size_t)y * outW + x) * 256 + icq * 8) =
            *reinterpret_cast<int4*>(res);
    }
}

// ---------------------------------------------------------------------------
// fp16 mma.sync implicit-GEMM conv, NHWC, cp.async 4-stage K32 ring,
// prefetch distance 3. Per stage: wait<2> (group s done), sync,
// CPA(s+3) into buffer retired at s-1, MMA(s). 2 CTAs/SM (160 KB smem).
// EPI: 0 = *is + bias, lrelu -> NHWC fp16
//      1 = *is + bias, lrelu -> NCHW f32
//      2 = out*rsqrt2 + acc*is*rsqrt2 -> NCHW f32
// ---------------------------------------------------------------------------
#define STAGE_BYTES 20480
#define CONV_SMEM (4 * STAGE_BYTES)

template <int KHW, int STRIDE, int EPI, int NS>
__global__ void __launch_bounds__(256, 2) conv_hmma(
    const __half* __restrict__ in, const __half* __restrict__ wt,
    const float* __restrict__ bias, void* __restrict__ outv,
    int INROW, int INIMG, int OC, int OH, int OW, int sigIdx) {
    extern __shared__ char smem[];
    const uint32_t sb = smem_u32(smem);

    const int tid = threadIdx.x;
    const int lane = tid & 31;
    const int wid = tid >> 5;
    const int wm = wid & 3;
    const int wn = wid >> 2;

    const int m0 = blockIdx.x * 128;
    const int ocb = blockIdx.y * 128;
    const int ohw = OH * OW;
    const int img = m0 / ohw;
    const int rbase = m0 - img * ohw;

    const int mIdx = tid >> 1;
    const int kq = tid & 1;
    const int m = rbase + mIdx;
    const int oh = m / OW;
    const int ow = m - oh * OW;
    const __half* abase = in + (size_t)img * INIMG + (size_t)(oh * STRIDE) * INROW +
                          (size_t)(ow * STRIDE) * 256 + kq * 16;
    const __half* bbase = wt + (size_t)(ocb + mIdx) * KHW * 256 + kq * 16;
    const uint32_t stsOff = (uint32_t)(mIdx * 80 + kq * 32);

    const int lg = lane >> 3, lr = lane & 7;
    const uint32_t rowsel = (uint32_t)(lr + ((lg >> 1) << 3));
    const uint32_t kcol = (uint32_t)((lg & 1) << 4);
    const uint32_t aLMr = (wm * 32 + rowsel) * 80 + kcol;
    const uint32_t bLMr = (wn * 64 + rowsel) * 80 + kcol;

    float c[2][8][4];
#pragma unroll
    for (int mb = 0; mb < 2; mb++)
#pragma unroll
        for (int nb = 0; nb < 8; nb++)
#pragma unroll
            for (int q = 0; q < 4; q++) c[mb][nb][q] = 0.f;

    auto CPA = [&](int s, uint32_t base) {
        const int kk = s * 32;
        const int khw = (KHW == 1) ? 0 : (kk >> 8);
        const int ic0 = kk - (khw << 8);
        int kh = 0, kw = 0;
        if (KHW == 9) { kh = khw / 3; kw = khw - kh * 3; }
        const __half* ap = abase + (size_t)kh * INROW + kw * 256 + ic0;
        cpa16(base + stsOff, ap);
        cpa16(base + stsOff + 16, ap + 8);
        const __half* bp = bbase + khw * 256 + ic0;
        cpa16(base + 10240 + stsOff, bp);
        cpa16(base + 10240 + stsOff + 16, bp + 8);
        cp_commit();
    };

    auto MMA = [&](uint32_t base) {
        const uint32_t aLM = base + aLMr;
        const uint32_t bLM = base + 10240 + bLMr;
#pragma unroll
        for (int k16 = 0; k16 < 2; k16++) {
            uint32_t a[2][4], b[8][2];
#pragma unroll
            for (int mb = 0; mb < 2; mb++) {
                uint32_t r[4];
                ldsm4(r, aLM + k16 * 32 + mb * 1280);
                a[mb][0] = r[0]; a[mb][1] = r[2]; a[mb][2] = r[1]; a[mb][3] = r[3];
            }
#pragma unroll
            for (int nbp = 0; nbp < 4; nbp++) {
                uint32_t r[4];
                ldsm4(r, bLM + k16 * 32 + nbp * 1280);
                b[nbp * 2][0] = r[0]; b[nbp * 2][1] = r[1];
                b[nbp * 2 + 1][0] = r[2]; b[nbp * 2 + 1][1] = r[3];
            }
#pragma unroll
            for (int mb = 0; mb < 2; mb++)
#pragma unroll
                for (int nb = 0; nb < 8; nb++)
                    mma16816(c[mb][nb], a[mb], b[nb]);
        }
    };

    // prologue: 3 stages in flight (buffers 0,1,2)
    CPA(0, sb);
    if (NS > 1) CPA(1, sb + STAGE_BYTES);
    if (NS > 2) CPA(2, sb + 2 * STAGE_BYTES);

    // 4-buffer ring, unrolled x4 so bases are compile-time constants.
    // Iteration s: wait for group s, sync, prefetch s+3 into buffer (s+3)%4
    // (retired at s-1, fenced by this sync), then MMA(s).
    for (int s0 = 0; s0 < NS; s0 += 4) {
#pragma unroll
        for (int j = 0; j < 4; j++) {
            const int s = s0 + j;
            if ((NS % 4 != 0) && s >= NS) break;
            if (s + 2 < NS) cp_wait<2>();
            else if (s + 1 < NS) cp_wait<1>();
            else cp_wait<0>();
            __syncthreads();
            if (s + 3 < NS) CPA(s + 3, sb + ((j + 3) & 3) * STAGE_BYTES);
            MMA(sb + j * STAGE_BYTES);
        }
    }
    __syncthreads();

    const float is = inv_sigma_of(sigIdx);
    const int erow = lane >> 2;
    const int ecolp = (lane & 3) * 2;

    if (EPI == 0) {
        __half* ob = (__half*)outv;
#pragma unroll
        for (int mb = 0; mb < 2; mb++) {
            const size_t mrow = (size_t)(m0 + wm * 32 + mb * 16 + erow);
#pragma unroll
            for (int nb = 0; nb < 8; nb++) {
                const int col = ocb + wn * 64 + nb * 8 + ecolp;
                const float bv0 = __ldg(bias + col);
                const float bv1 = __ldg(bias + col + 1);
                const float* cc = c[mb][nb];
                float v0 = fmaf(cc[0], is, bv0), v1 = fmaf(cc[1], is, bv1);
                float v2 = fmaf(cc[2], is, bv0), v3 = fmaf(cc[3], is, bv1);
                v0 = v0 > 0.f ? v0 : 0.2f * v0;
                v1 = v1 > 0.f ? v1 : 0.2f * v1;
                v2 = v2 > 0.f ? v2 : 0.2f * v2;
                v3 = v3 > 0.f ? v3 : 0.2f * v3;
                __half2 h0 = __floats2half2_rn(v0, v1);
                __half2 h1 = __floats2half2_rn(v2, v3);
                *reinterpret_cast<__half2*>(ob + mrow * 256 + col) = h0;
                *reinterpret_cast<__half2*>(ob + (mrow + 8) * 256 + col) = h1;
            }
        }
    } else {
        const float sc = is * RSQRT2;
        for (int nc = 0; nc < 4; nc++) {
            if (wn == (nc >> 1)) {
                const int nbBase = (nc & 1) * 4;
#pragma unroll
                for (int mb = 0; mb < 2; mb++) {
                    const int mrow = wm * 32 + mb * 16 + erow;
#pragma unroll
                    for (int j = 0; j < 4; j++) {
                        const int nb = nbBase + j;
                        const int ocl = j * 8 + ecolp;
                        const float* cc = c[mb][nb];
                        sts32f(sb + (uint32_t)(ocl * 544 + mrow * 4), cc[0]);
                        sts32f(sb + (uint32_t)((ocl + 1) * 544 + mrow * 4), cc[1]);
                        sts32f(sb + (uint32_t)(ocl * 544 + (mrow + 8) * 4), cc[2]);
                        sts32f(sb + (uint32_t)((ocl + 1) * 544 + (mrow + 8) * 4), cc[3]);
                    }
                }
            }
            __syncthreads();
#pragma unroll
            for (int p = 0; p < 4; p++) {
                const int idx = p * 256 + tid;
                const int ocl = idx >> 5;
                const int mq = (idx & 31) * 4;
                float4 v = lds128f(sb + (uint32_t)(ocl * 544 + mq * 4));
                const int oc = ocb + nc * 32 + ocl;
                const size_t go = ((size_t)img * OC + oc) * ohw + rbase + mq;
                if (EPI == 1) {
                    const float bv = __ldg(bias + oc);
                    v.x = fmaf(v.x, is, bv); v.y = fmaf(v.y, is, bv);
                    v.z = fmaf(v.z, is, bv); v.w = fmaf(v.w, is, bv);
                    v.x = v.x > 0.f ? v.x : 0.2f * v.x;
                    v.y = v.y > 0.f ? v.y : 0.2f * v.y;
                    v.z = v.z > 0.f ? v.z : 0.2f * v.z;
                    v.w = v.w > 0.f ? v.w : 0.2f * v.w;
                    *reinterpret_cast<float4*>((float*)outv + go) = v;
                } else {
                    float* op = (float*)outv + go;
                    float4 o = *reinterpret_cast<const float4*>(op);
                    o.x = fmaf(v.x, sc, o.x * RSQRT2);
                    o.y = fmaf(v.y, sc, o.y * RSQRT2);
                    o.z = fmaf(v.z, sc, o.z * RSQRT2);
                    o.w = fmaf(v.w, sc, o.w * RSQRT2);
                    *reinterpret_cast<float4*>(op) = o;
                }
            }
            __syncthreads();
        }
    }
}

// ---------------------------------------------------------------------------
extern "C" void kernel_launch(void* const* d_in, const int* in_sizes, int n_in,
                              void* d_out, int out_size) {
    const float* x   = (const float*)d_in[0];
    const float* w1  = (const float*)d_in[1];
    const float* u1  = (const float*)d_in[2];
    const float* b1  = (const float*)d_in[4];
    const float* w2  = (const float*)d_in[5];
    const float* u2  = (const float*)d_in[6];
    const float* b2  = (const float*)d_in[8];
    const float* wsk = (const float*)d_in[9];
    const float* us  = (const float*)d_in[10];
    float* out = (float*)d_out;

    __half *xpad, *bufA, *bufB, *bufC, *wt1, *wt2, *wts;
    cudaGetSymbolAddress((void**)&xpad, g_xpad);
    cudaGetSymbolAddress((void**)&bufA, g_bufA);
    cudaGetSymbolAddress((void**)&bufB, g_bufB);
    cudaGetSymbolAddress((void**)&bufC, g_bufC);
    cudaGetSymbolAddress((void**)&wt1, g_wt1);
    cudaGetSymbolAddress((void**)&wt2, g_wt2);
    cudaGetSymbolAddress((void**)&wts, g_wts);

    cudaFuncSetAttribute(conv_hmma<9, 1, 0, 72>,
                         cudaFuncAttributeMaxDynamicSharedMemorySize, CONV_SMEM);
    cudaFuncSetAttribute(conv_hmma<9, 2, 1, 72>,
                         cudaFuncAttributeMaxDynamicSharedMemorySize, CONV_SMEM);
    cudaFuncSetAttribute(conv_hmma<1, 2, 2, 8>,
                         cudaFuncAttributeMaxDynamicSharedMemorySize, CONV_SMEM);

    // #0: t = W^T u
    sn_tk_all<<<dim3(9, 8, 3), 256>>>(w1, u1, w2, u2, wsk, us);
    // #1: ||Wt||^2, ||t||^2
    sn_sk_all<<<dim3(512, 3), 256>>>(w1, w2, wsk);
    // #2: pad/transpose x + transpose/convert weights
    padprep<<<PADPREP_BLOCKS, 256>>>(x, xpad, w1, w2, wsk);
    // #3: conv1 (ncu sampling slot)
    conv_hmma<9, 1, 0, 72><<<dim3(512, 2), 256, CONV_SMEM>>>(
        xpad, wt1, b1, bufA, 66 * 256, 66 * 66 * 256, 256, 64, 64, 0);
    // #4: blurB (skip path): xpad (66) -> bufB (63), OFF=0
    {
        const int groups = (63 + 3) / 4;
        const int t = 16 * 63 * groups * 32;
        blur4_nhwc<false, 0><<<(t + 255) / 256, 256>>>(xpad, bufB, 66, 63, groups);
    }
    // #5: blurC: bufA (64) -> bufC (65), OFF=-2
    {
        const int groups = (65 + 3) / 4;
        const int t = 16 * 65 * groups * 32;
        blur4_nhwc<true, -2><<<(t + 255) / 256, 256>>>(bufA, bufC, 64, 65, groups);
    }
    // #6: conv2 -> out NCHW f32
    conv_hmma<9, 2, 1, 72><<<dim3(128, 4), 256, CONV_SMEM>>>(
        bufC, wt2, b2, out, 65 * 256, 65 * 65 * 256, 512, 32, 32, 1);
    // #7: skip conv: out = out*rsqrt2 + acc*is*rsqrt2
    conv_hmma<1, 2, 2, 8><<<dim3(128, 4), 256, CONV_SMEM>>>(
        bufB, wts, nullptr, out, 63 * 256, 63 * 63 * 256, 512, 32, 32, 2);
    // #8: reset SN accumulators for the next replay
    sn_zero_tail<<<1, 256>>>();
}

// round 16
// speedup vs baseline: 1.1984x; 1.0372x over previous
#include <cuda_runtime.h>
#include <cuda_fp16.h>
#include <math.h>
#include <stdint.h>

#define RSQRT2 0.70710678118654752f

// ---------------- device scratch (allocation-free rule) ----------------
// BSS zero-init is load-time state. g_t*/g_nt2/g_ns2 are re-zeroed at the END
// of every kernel_launch (graph tail), so each replay starts from zeros.
// xpad's halo is never written by any kernel and stays zero forever.
__device__ float g_t1[2304];
__device__ float g_t2[2304];
__device__ float g_t3[256];
__device__ float g_nt2[3];
__device__ float g_ns2[3];
__device__ __half g_xpad[16 * 66 * 66 * 256];   // NHWC padded fp16 x (halo always 0)
__device__ __half g_bufA[16 * 64 * 64 * 256];   // conv1 output NHWC
__device__ __half g_bufB[16 * 63 * 63 * 256];   // blur(x,pad1) NHWC
__device__ __half g_bufC[16 * 65 * 65 * 256];   // blur(conv1,pad2) NHWC
__device__ __half g_wt1[256 * 9 * 256];         // [oc][khw][ic]  (unscaled fp16)
__device__ __half g_wt2[512 * 9 * 256];
__device__ __half g_wts[512 * 256];

// ---------------- helpers ----------------
__device__ __forceinline__ float warp_sum(float v) {
#pragma unroll
    for (int o = 16; o; o >>= 1) v += __shfl_down_sync(0xffffffffu, v, o);
    return v;
}

__device__ float block_sum(float v) {
    __shared__ float red[32];
    int lane = threadIdx.x & 31, w = threadIdx.x >> 5;
    v = warp_sum(v);
    if (lane == 0) red[w] = v;
    __syncthreads();
    float r = 0.f;
    if (w == 0) {
        int nw = (blockDim.x + 31) >> 5;
        r = (lane < nw) ? red[lane] : 0.f;
        r = warp_sum(r);
    }
    __syncthreads();
    return r;
}

__device__ __forceinline__ uint32_t smem_u32(const void* p) {
    uint32_t a;
    asm("{ .reg .u64 t; cvta.to.shared.u64 t, %1; cvt.u32.u64 %0, t; }" : "=r"(a) : "l"(p));
    return a;
}

__device__ __forceinline__ void sts32f(uint32_t a, float v) {
    asm volatile("st.shared.b32 [%0], %1;" :: "r"(a), "f"(v) : "memory");
}
__device__ __forceinline__ float4 lds128f(uint32_t a) {
    float4 v;
    asm volatile("ld.shared.v4.f32 {%0,%1,%2,%3}, [%4];"
                 : "=f"(v.x), "=f"(v.y), "=f"(v.z), "=f"(v.w) : "r"(a));
    return v;
}

__device__ __forceinline__ void cpa16(uint32_t s, const void* g) {
    asm volatile("cp.async.cg.shared.global [%0], [%1], 16;" :: "r"(s), "l"(g) : "memory");
}
__device__ __forceinline__ void cp_commit() {
    asm volatile("cp.async.commit_group;" ::: "memory");
}
template <int N>
__device__ __forceinline__ void cp_wait() {
    asm volatile("cp.async.wait_group %0;" :: "n"(N) : "memory");
}

__device__ __forceinline__ void ldsm4(uint32_t* r, uint32_t addr) {
    asm volatile("ldmatrix.sync.aligned.m8n8.x4.shared.b16 {%0,%1,%2,%3}, [%4];"
                 : "=r"(r[0]), "=r"(r[1]), "=r"(r[2]), "=r"(r[3]) : "r"(addr));
}

__device__ __forceinline__ void mma16816(float* c, const uint32_t* a, const uint32_t* b) {
    asm volatile(
        "mma.sync.aligned.m16n8k16.row.col.f32.f16.f16.f32 "
        "{%0,%1,%2,%3}, {%4,%5,%6,%7}, {%8,%9}, {%0,%1,%2,%3};"
        : "+f"(c[0]), "+f"(c[1]), "+f"(c[2]), "+f"(c[3])
        : "r"(a[0]), "r"(a[1]), "r"(a[2]), "r"(a[3]), "r"(b[0]), "r"(b[1]));
}

__device__ __forceinline__ float inv_sigma_of(int sigIdx) {
    float nt = sqrtf(g_nt2[sigIdx]);
    float nwt = sqrtf(g_ns2[sigIdx]);
    float nwv = nwt / (nt + 1e-12f);
    return (nwv + 1e-12f) / (nwv * nwv);
}

// ---------------- spectral norm (fused across all 3 weights) ----------------
__global__ void sn_tk_all(const float* __restrict__ w1, const float* __restrict__ u1,
                          const float* __restrict__ w2, const float* __restrict__ u2,
                          const float* __restrict__ ws, const float* __restrict__ us) {
    const int wsel = blockIdx.z;
    const float* W = (wsel == 0) ? w1 : (wsel == 1) ? w2 : ws;
    const float* u = (wsel == 0) ? u1 : (wsel == 1) ? u2 : us;
    float* t = (wsel == 0) ? g_t1 : (wsel == 1) ? g_t2 : g_t3;
    const int H = (wsel == 0) ? 256 : 512;
    const int K = (wsel == 2) ? 256 : 2304;
    int j = blockIdx.x * 256 + threadIdx.x;
    if (j >= K) return;
    int chunk = H >> 3;
    int i0 = blockIdx.y * chunk;
    int i1 = i0 + chunk;
    float s = 0.f;
    for (int i = i0; i < i1; i++)
        s = fmaf(W[(size_t)i * K + j], __ldg(u + i), s);
    atomicAdd(t + j, s);
}

__global__ void sn_sk_all(const float* __restrict__ w1, const float* __restrict__ w2,
                          const float* __restrict__ ws) {
    const int wsel = blockIdx.y;
    const float* W = (wsel == 0) ? w1 : (wsel == 1) ? w2 : ws;
    const float* t = (wsel == 0) ? g_t1 : (wsel == 1) ? g_t2 : g_t3;
    const int H = (wsel == 0) ? 256 : 512;
    const int K = (wsel == 2) ? 256 : 2304;
    const int i = blockIdx.x;
    if (i >= H) return;
    float s = 0.f;
    for (int j = threadIdx.x; j < K; j += blockDim.x)
        s = fmaf(W[(size_t)i * K + j], __ldg(t + j), s);
    s = block_sum(s);
    if (threadIdx.x == 0) atomicAdd(&g_ns2[wsel], s * s);
    if (i == 0) {
        float a = 0.f;
        for (int j = threadIdx.x; j < K; j += blockDim.x) {
            float tv = __ldg(t + j);
            a = fmaf(tv, tv, a);
        }
        a = block_sum(a);
        if (threadIdx.x == 0) atomicAdd(&g_nt2[wsel], a);
    }
}

__global__ void sn_zero_tail() {
    int t = threadIdx.x;
    for (int i = t; i < 2304; i += 256) { g_t1[i] = 0.f; g_t2[i] = 0.f; }
    if (t < 256) g_t3[t] = 0.f;
    if (t < 3) { g_nt2[t] = 0.f; g_ns2[t] = 0.f; }
}

// ---------------- merged pad + weight prep ----------------
#define PAD_BLOCKS 8192
#define PREP_N1 (256 * 256 * 9)
#define PREP_N2 (512 * 256 * 9)
#define PREP_NS (512 * 256)
#define PREP_TOTAL (PREP_N1 + PREP_N2 + PREP_NS)
#define PREP_BLOCKS ((PREP_TOTAL + 255) / 256)
#define PADPREP_BLOCKS (PAD_BLOCKS + PREP_BLOCKS)

__global__ void padprep(const float* __restrict__ x, __half* __restrict__ xp,
                        const float* __restrict__ w1, const float* __restrict__ w2,
                        const float* __restrict__ ws) {
    __shared__ float sm[64][33];
    const int bid = blockIdx.x;
    const int tid = threadIdx.x;
    if (bid < PAD_BLOCKS) {
        const int wt = bid & 1;
        const int ict = (bid >> 1) & 3;
        const int plane = bid >> 3;
        const int img = plane >> 6, h = plane & 63;
        const int w0 = wt * 32, ic0 = ict * 64;
        const int icl = tid >> 5, wl = tid & 31;
        const float* xb = x + (((size_t)img * 256 + ic0) * 64 + h) * 64 + w0;
#pragma unroll
        for (int r = 0; r < 8; r++)
            sm[icl + r * 8][wl] = xb[(size_t)(icl + r * 8) * 4096 + wl];
        __syncthreads();
        const int wIdx = tid >> 3, icq = tid & 7;
        __half hv[8];
#pragma unroll
        for (int k = 0; k < 8; k++) hv[k] = __float2half_rn(sm[icq * 8 + k][wIdx]);
        *reinterpret_cast<int4*>(
            xp + (((size_t)img * 66 + h + 1) * 66 + (w0 + wIdx + 1)) * 256 + ic0 + icq * 8) =
            *reinterpret_cast<int4*>(hv);
    } else {
        int idx = (bid - PAD_BLOCKS) * 256 + tid;
        if (idx >= PREP_TOTAL) return;
        const float* w;
        __half* wtp;
        int KHW, li;
        if (idx < PREP_N1) {
            w = w1; wtp = g_wt1; KHW = 9; li = idx;
        } else if (idx < PREP_N1 + PREP_N2) {
            w = w2; wtp = g_wt2; KHW = 9; li = idx - PREP_N1;
        } else {
            w = ws; wtp = g_wts; KHW = 1; li = idx - PREP_N1 - PREP_N2;
        }
        int khw = li % KHW;
        int t = li / KHW;
        int ic = t & 255;
        int oc = t >> 8;
        wtp[((size_t)oc * KHW + khw) * 256 + ic] = __float2half_rn(w[li]);
    }
}

// ---------------- 4x4 binomial blur, NHWC, 4 x-outputs x 8ch per thread ------
template <bool CHECK, int OFF>
__global__ void blur4_nhwc(const __half* __restrict__ in, __half* __restrict__ out,
                           int inW, int outW, int groups) {
    int idx = blockIdx.x * blockDim.x + threadIdx.x;
    int total = 16 * outW * groups * 32;
    if (idx >= total) return;
    const int icq = idx & 31;
    int t = idx >> 5;
    const int xg = t % groups; t /= groups;
    const int y = t % outW;
    const int img = t / outW;
    const int x0 = xg * 4;
    const __half* ib = in + (size_t)img * inW * inW * 256 + icq * 8;
    const float kv[4] = {1.f, 3.f, 3.f, 1.f};
    float acc[4][8];
#pragma unroll
    for (int o = 0; o < 4; o++)
#pragma unroll
        for (int q = 0; q < 8; q++) acc[o][q] = 0.f;
#pragma unroll
    for (int i = 0; i < 4; i++) {
        const int yy = y + i + OFF;
        if ((unsigned)yy >= (unsigned)inW) continue;
        const __half* rb = ib + (size_t)yy * inW * 256;
#pragma unroll
        for (int c = 0; c < 7; c++) {
            const int xx = x0 + c + OFF;
            if ((unsigned)xx >= (unsigned)inW) continue;
            int4 v = *reinterpret_cast<const int4*>(rb + (size_t)xx * 256);
            const __half* h = reinterpret_cast<const __half*>(&v);
            float hv[8];
#pragma unroll
            for (int q = 0; q < 8; q++) hv[q] = __half2float(h[q]);
#pragma unroll
            for (int o = 0; o < 4; o++) {
                const int j = c - o;
                if (j >= 0 && j < 4) {
                    const float w = kv[i] * kv[j];
#pragma unroll
                    for (int q = 0; q < 8; q++) acc[o][q] = fmaf(w, hv[q], acc[o][q]);
                }
            }
        }
    }
#pragma unroll
    for (int o = 0; o < 4; o++) {
        const int x = x0 + o;
        if (x >= outW) break;
        __half res[8];
#pragma unroll
        for (int q = 0; q < 8; q++) res[q] = __float2half_rn(acc[o][q] * (1.f / 64.f));
        *reinterpret_cast<int4*>(
            out + ((size_t)img * outW * outW + (size_t)y * outW + x) * 256 + icq * 8) =
            *reinterpret_cast<int4*>(res);
    }
}

// ---------------------------------------------------------------------------
// fp16 mma.sync implicit-GEMM conv, NHWC, cp.async 4-stage K32 ring.
// Block tile M=128 x N=64, warp tile 32m x 32n (8 warps), c[2][4][4] -> ~70
// regs -> 3 CTAs/SM (24 warps, occ ~35%). Stage = A 10240 + B 5120 = 15360 B;
// ring 61440 B; x3 CTAs = 184 KB smem.
// EPI: 0 = *is + bias, lrelu -> NHWC fp16
//      1 = *is + bias, lrelu -> NCHW f32
//      2 = out*rsqrt2 + acc*is*rsqrt2 -> NCHW f32
// ---------------------------------------------------------------------------
#define A_BYTES 10240
#define STAGE_BYTES 15360
#define CONV_SMEM (4 * STAGE_BYTES)

template <int KHW, int STRIDE, int EPI, int NS>
__global__ void __launch_bounds__(256, 3) conv_hmma(
    const __half* __restrict__ in, const __half* __restrict__ wt,
    const float* __restrict__ bias, void* __restrict__ outv,
    int INROW, int INIMG, int OC, int OH, int OW, int sigIdx) {
    extern __shared__ char smem[];
    const uint32_t sb = smem_u32(smem);

    const int tid = threadIdx.x;
    const int lane = tid & 31;
    const int wid = tid >> 5;
    const int wm = wid & 3;
    const int wn = wid >> 2;

    const int m0 = blockIdx.x * 128;
    const int ocb = blockIdx.y * 64;
    const int ohw = OH * OW;
    const int img = m0 / ohw;
    const int rbase = m0 - img * ohw;

    // A gather: thread -> (pixel row mIdx, 16B half kq)
    const int mIdx = tid >> 1;
    const int kq = tid & 1;
    const int m = rbase + mIdx;
    const int oh = m / OW;
    const int ow = m - oh * OW;
    const __half* abase = in + (size_t)img * INIMG + (size_t)(oh * STRIDE) * INROW +
                          (size_t)(ow * STRIDE) * 256 + kq * 16;
    const uint32_t aOff = (uint32_t)(mIdx * 80 + kq * 32);
    // B gather: threads 0..127 -> (oc row bIdx, half kq)
    const int bIdx = (tid & 127) >> 1;
    const __half* bbase = wt + (size_t)(ocb + bIdx) * KHW * 256 + kq * 16;
    const uint32_t bOff = (uint32_t)(bIdx * 80 + kq * 32);
    const bool doB = (tid < 128);

    // ldmatrix addressing (non-trans), pitch 80 (conflict-free)
    const int lg = lane >> 3, lr = lane & 7;
    const uint32_t rowsel = (uint32_t)(lr + ((lg >> 1) << 3));
    const uint32_t kcol = (uint32_t)((lg & 1) << 4);
    const uint32_t aLMr = (wm * 32 + rowsel) * 80 + kcol;
    const uint32_t bLMr = (wn * 32 + rowsel) * 80 + kcol;

    float c[2][4][4];
#pragma unroll
    for (int mb = 0; mb < 2; mb++)
#pragma unroll
        for (int nb = 0; nb < 4; nb++)
#pragma unroll
            for (int q = 0; q < 4; q++) c[mb][nb][q] = 0.f;

    auto CPA = [&](int s, uint32_t base) {
        const int kk = s * 32;
        const int khw = (KHW == 1) ? 0 : (kk >> 8);
        const int ic0 = kk - (khw << 8);
        int kh = 0, kw = 0;
        if (KHW == 9) { kh = khw / 3; kw = khw - kh * 3; }
        const __half* ap = abase + (size_t)kh * INROW + kw * 256 + ic0;
        cpa16(base + aOff, ap);
        cpa16(base + aOff + 16, ap + 8);
        if (doB) {
            const __half* bp = bbase + khw * 256 + ic0;
            cpa16(base + A_BYTES + bOff, bp);
            cpa16(base + A_BYTES + bOff + 16, bp + 8);
        }
        cp_commit();
    };

    auto MMA = [&](uint32_t base) {
        const uint32_t aLM = base + aLMr;
        const uint32_t bLM = base + A_BYTES + bLMr;
#pragma unroll
        for (int k16 = 0; k16 < 2; k16++) {
            uint32_t a[2][4], b[4][2];
#pragma unroll
            for (int mb = 0; mb < 2; mb++) {
                uint32_t r[4];
                ldsm4(r, aLM + k16 * 32 + mb * 1280);
                a[mb][0] = r[0]; a[mb][1] = r[2]; a[mb][2] = r[1]; a[mb][3] = r[3];
            }
#pragma unroll
            for (int nbp = 0; nbp < 2; nbp++) {
                uint32_t r[4];
                ldsm4(r, bLM + k16 * 32 + nbp * 1280);
                b[nbp * 2][0] = r[0]; b[nbp * 2][1] = r[1];
                b[nbp * 2 + 1][0] = r[2]; b[nbp * 2 + 1][1] = r[3];
            }
#pragma unroll
            for (int mb = 0; mb < 2; mb++)
#pragma unroll
                for (int nb = 0; nb < 4; nb++)
                    mma16816(c[mb][nb], a[mb], b[nb]);
        }
    };

    // prologue: 3 stages in flight (buffers 0,1,2)
    CPA(0, sb);
    if (NS > 1) CPA(1, sb + STAGE_BYTES);
    if (NS > 2) CPA(2, sb + 2 * STAGE_BYTES);

    // 4-buffer ring, unrolled x4 so bases are compile-time constants.
    for (int s0 = 0; s0 < NS; s0 += 4) {
#pragma unroll
        for (int j = 0; j < 4; j++) {
            const int s = s0 + j;
            if ((NS % 4 != 0) && s >= NS) break;
            if (s + 2 < NS) cp_wait<2>();
            else if (s + 1 < NS) cp_wait<1>();
            else cp_wait<0>();
            __syncthreads();
            if (s + 3 < NS) CPA(s + 3, sb + ((j + 3) & 3) * STAGE_BYTES);
            MMA(sb + j * STAGE_BYTES);
        }
    }
    __syncthreads();

    const float is = inv_sigma_of(sigIdx);
    const int erow = lane >> 2;
    const int ecolp = (lane & 3) * 2;

    if (EPI == 0) {
        __half* ob = (__half*)outv;
#pragma unroll
        for (int mb = 0; mb < 2; mb++) {
            const size_t mrow = (size_t)(m0 + wm * 32 + mb * 16 + erow);
#pragma unroll
            for (int nb = 0; nb < 4; nb++) {
                const int col = ocb + wn * 32 + nb * 8 + ecolp;
                const float bv0 = __ldg(bias + col);
                const float bv1 = __ldg(bias + col + 1);
                const float* cc = c[mb][nb];
                float v0 = fmaf(cc[0], is, bv0), v1 = fmaf(cc[1], is, bv1);
                float v2 = fmaf(cc[2], is, bv0), v3 = fmaf(cc[3], is, bv1);
                v0 = v0 > 0.f ? v0 : 0.2f * v0;
                v1 = v1 > 0.f ? v1 : 0.2f * v1;
                v2 = v2 > 0.f ? v2 : 0.2f * v2;
                v3 = v3 > 0.f ? v3 : 0.2f * v3;
                __half2 h0 = __floats2half2_rn(v0, v1);
                __half2 h1 = __floats2half2_rn(v2, v3);
                *reinterpret_cast<__half2*>(ob + mrow * 256 + col) = h0;
                *reinterpret_cast<__half2*>(ob + (mrow + 8) * 256 + col) = h1;
            }
        }
    } else {
        const float sc = is * RSQRT2;
        for (int nc = 0; nc < 2; nc++) {
            if (wn == nc) {
#pragma unroll
                for (int mb = 0; mb < 2; mb++) {
                    const int mrow = wm * 32 + mb * 16 + erow;
#pragma unroll
                    for (int j = 0; j < 4; j++) {
                        const int ocl = j * 8 + ecolp;
                        const float* cc = c[mb][j];
                        sts32f(sb + (uint32_t)(ocl * 544 + mrow * 4), cc[0]);
                        sts32f(sb + (uint32_t)((ocl + 1) * 544 + mrow * 4), cc[1]);
                        sts32f(sb + (uint32_t)(ocl * 544 + (mrow + 8) * 4), cc[2]);
                        sts32f(sb + (uint32_t)((ocl + 1) * 544 + (mrow + 8) * 4), cc[3]);
                    }
                }
            }
            __syncthreads();
#pragma unroll
            for (int p = 0; p < 4; p++) {
                const int idx = p * 256 + tid;
                const int ocl = idx >> 5;
                const int mq = (idx & 31) * 4;
                float4 v = lds128f(sb + (uint32_t)(ocl * 544 + mq * 4));
                const int oc = ocb + nc * 32 + ocl;
                const size_t go = ((size_t)img * OC + oc) * ohw + rbase + mq;
                if (EPI == 1) {
                    const float bv = __ldg(bias + oc);
                    v.x = fmaf(v.x, is, bv); v.y = fmaf(v.y, is, bv);
                    v.z = fmaf(v.z, is, bv); v.w = fmaf(v.w, is, bv);
                    v.x = v.x > 0.f ? v.x : 0.2f * v.x;
                    v.y = v.y > 0.f ? v.y : 0.2f * v.y;
                    v.z = v.z > 0.f ? v.z : 0.2f * v.z;
                    v.w = v.w > 0.f ? v.w : 0.2f * v.w;
                    *reinterpret_cast<float4*>((float*)outv + go) = v;
                } else {
                    float* op = (float*)outv + go;
                    float4 o = *reinterpret_cast<const float4*>(op);
                    o.x = fmaf(v.x, sc, o.x * RSQRT2);
                    o.y = fmaf(v.y, sc, o.y * RSQRT2);
                    o.z = fmaf(v.z, sc, o.z * RSQRT2);
                    o.w = fmaf(v.w, sc, o.w * RSQRT2);
                    *reinterpret_cast<float4*>(op) = o;
                }
            }
            __syncthreads();
        }
    }
}

// ---------------------------------------------------------------------------
extern "C" void kernel_launch(void* const* d_in, const int* in_sizes, int n_in,
                              void* d_out, int out_size) {
    const float* x   = (const float*)d_in[0];
    const float* w1  = (const float*)d_in[1];
    const float* u1  = (const float*)d_in[2];
    const float* b1  = (const float*)d_in[4];
    const float* w2  = (const float*)d_in[5];
    const float* u2  = (const float*)d_in[6];
    const float* b2  = (const float*)d_in[8];
    const float* wsk = (const float*)d_in[9];
    const float* us  = (const float*)d_in[10];
    float* out = (float*)d_out;

    __half *xpad, *bufA, *bufB, *bufC, *wt1, *wt2, *wts;
    cudaGetSymbolAddress((void**)&xpad, g_xpad);
    cudaGetSymbolAddress((void**)&bufA, g_bufA);
    cudaGetSymbolAddress((void**)&bufB, g_bufB);
    cudaGetSymbolAddress((void**)&bufC, g_bufC);
    cudaGetSymbolAddress((void**)&wt1, g_wt1);
    cudaGetSymbolAddress((void**)&wt2, g_wt2);
    cudaGetSymbolAddress((void**)&wts, g_wts);

    cudaFuncSetAttribute(conv_hmma<9, 1, 0, 72>,
                         cudaFuncAttributeMaxDynamicSharedMemorySize, CONV_SMEM);
    cudaFuncSetAttribute(conv_hmma<9, 2, 1, 72>,
                         cudaFuncAttributeMaxDynamicSharedMemorySize, CONV_SMEM);
    cudaFuncSetAttribute(conv_hmma<1, 2, 2, 8>,
                         cudaFuncAttributeMaxDynamicSharedMemorySize, CONV_SMEM);

    // #0: t = W^T u
    sn_tk_all<<<dim3(9, 8, 3), 256>>>(w1, u1, w2, u2, wsk, us);
    // #1: ||Wt||^2, ||t||^2
    sn_sk_all<<<dim3(512, 3), 256>>>(w1, w2, wsk);
    // #2: pad/transpose x + transpose/convert weights
    padprep<<<PADPREP_BLOCKS, 256>>>(x, xpad, w1, w2, wsk);
    // #3: conv1 (ncu sampling slot)
    conv_hmma<9, 1, 0, 72><<<dim3(512, 4), 256, CONV_SMEM>>>(
        xpad, wt1, b1, bufA, 66 * 256, 66 * 66 * 256, 256, 64, 64, 0);
    // #4: blurB (skip path): xpad (66) -> bufB (63), OFF=0
    {
        const int groups = (63 + 3) / 4;
        const int t = 16 * 63 * groups * 32;
        blur4_nhwc<false, 0><<<(t + 255) / 256, 256>>>(xpad, bufB, 66, 63, groups);
    }
    // #5: blurC: bufA (64) -> bufC (65), OFF=-2
    {
        const int groups = (65 + 3) / 4;
        const int t = 16 * 65 * groups * 32;
        blur4_nhwc<true, -2><<<(t + 255) / 256, 256>>>(bufA, bufC, 64, 65, groups);
    }
    // #6: conv2 -> out NCHW f32
    conv_hmma<9, 2, 1, 72><<<dim3(128, 8), 256, CONV_SMEM>>>(
        bufC, wt2, b2, out, 65 * 256, 65 * 65 * 256, 512, 32, 32, 1);
    // #7: skip conv: out = out*rsqrt2 + acc*is*rsqrt2
    conv_hmma<1, 2, 2, 8><<<dim3(128, 8), 256, CONV_SMEM>>>(
        bufB, wts, nullptr, out, 63 * 256, 63 * 63 * 256, 512, 32, 32, 2);
    // #8: reset SN accumulators for the next replay
    sn_zero_tail<<<1, 256>>>();
}